// round 1
// baseline (speedup 1.0000x reference)
#include <cuda_runtime.h>

// LinAngularAttention  fp32 baseline
// x:[8,256,64,64], w_qkv:[768,256], b_qkv:[768], w_proj:[256,256], b_proj:[256], w_dconv:[8,1,9,1]
// out:[8,256,64,64]

#define NB 8
#define CC 256
#define HH 8
#define DD 32
#define LL 4096
#define J3 768
#define NH (NB*HH)
#define SPLIT 16

__device__ float g_qkv[(size_t)NB * LL * J3];   // [N, L, 3C]  (3C order: q|k|v, each h*32+d)
__device__ float g_attn[NH * DD * DD];          // [N*H, D, D]
__device__ float g_mid[(size_t)NB * LL * CC];   // [N, L, C]

// ---------------------------------------------------------------------------
// QKV GEMM: qkv[m, j] = sum_c x[n, c, l] * Wq[j, c] + bq[j]    (m = n*L + l)
// 64x64 block tile, BK=16, 256 threads, 4x4 per thread.
// thread tx -> j (output fast dim), ty -> m.
// ---------------------------------------------------------------------------
__global__ __launch_bounds__(256) void k_gemm_qkv(const float* __restrict__ x,
                                                  const float* __restrict__ W,
                                                  const float* __restrict__ bias) {
    __shared__ float As[16][64];   // As[kk][i(m)]
    __shared__ float Bs[16][64];   // Bs[kk][j]
    const int j0 = blockIdx.x * 64;          // 0..704
    const int m0 = blockIdx.y * 64;          // 0..32704
    const int n  = m0 >> 12;
    const int l0 = m0 & 4095;
    const int tid = threadIdx.x;
    const int tx = tid & 15, ty = tid >> 4;
    const float* xb = x + (size_t)n * CC * LL;

    float acc[4][4] = {};
    for (int k0 = 0; k0 < CC; k0 += 16) {
        {   // A: As[kk][i] = x[n, k0+kk, l0+i]   (contiguous in l)
            int idx = tid * 4;
            int kk = idx >> 6, i = idx & 63;
            float4 va = *(const float4*)(xb + (size_t)(k0 + kk) * LL + l0 + i);
            *(float4*)&As[kk][i] = va;
        }
        {   // B: Bs[kk][j] = W[(j0+j)*256 + k0+kk]  (transpose during load)
            int j = tid >> 2, kkb = (tid & 3) * 4;
            float4 vb = *(const float4*)(W + (size_t)(j0 + j) * CC + k0 + kkb);
            Bs[kkb + 0][j] = vb.x; Bs[kkb + 1][j] = vb.y;
            Bs[kkb + 2][j] = vb.z; Bs[kkb + 3][j] = vb.w;
        }
        __syncthreads();
#pragma unroll
        for (int kk = 0; kk < 16; kk++) {
            float4 a = *(const float4*)&As[kk][ty * 4];
            float4 b = *(const float4*)&Bs[kk][tx * 4];
            float av[4] = {a.x, a.y, a.z, a.w};
            float bv[4] = {b.x, b.y, b.z, b.w};
#pragma unroll
            for (int i = 0; i < 4; i++)
#pragma unroll
                for (int j = 0; j < 4; j++) acc[i][j] += av[i] * bv[j];
        }
        __syncthreads();
    }
    float4 bb = *(const float4*)(bias + j0 + tx * 4);
    float bv[4] = {bb.x, bb.y, bb.z, bb.w};
#pragma unroll
    for (int i = 0; i < 4; i++) {
        int m = m0 + ty * 4 + i;
        float4 o = make_float4(acc[i][0] + bv[0], acc[i][1] + bv[1],
                               acc[i][2] + bv[2], acc[i][3] + bv[3]);
        *(float4*)(g_qkv + (size_t)m * J3 + j0 + tx * 4) = o;
    }
}

// ---------------------------------------------------------------------------
__global__ void k_zero_attn() {
    int i = blockIdx.x * 256 + threadIdx.x;
    if (i < NH * DD * DD) g_attn[i] = 0.f;
}

// attn[nh, d, e] += sum_l knorm[l,d] * v[l,e], split over L into SPLIT chunks.
__global__ __launch_bounds__(256) void k_attn() {
    __shared__ float  ks[32][32];
    __shared__ float4 vs4[32][8];
    const int nh = blockIdx.x;              // 0..63
    const int chunk = blockIdx.y;           // 0..SPLIT-1
    const int n = nh >> 3, hh = nh & 7;
    const int tid = threadIdx.x;
    const int wid = tid >> 5, lane = tid & 31;
    const int d = tid >> 3, e4 = tid & 7;   // thread owns (d, 4e) pairs
    const int lbase = chunk * (LL / SPLIT);
    const float* qb = g_qkv + (size_t)n * LL * J3;

    float acc[4] = {};
    for (int t0 = 0; t0 < LL / SPLIT; t0 += 32) {
#pragma unroll
        for (int rr = 0; rr < 4; rr++) {
            int row = wid * 4 + rr;
            const float* rowp = qb + (size_t)(lbase + t0 + row) * J3 + hh * DD;
            float kv = rowp[CC + lane];       // k
            float vv = rowp[2 * CC + lane];   // v
            float s = kv * kv;
#pragma unroll
            for (int off = 16; off; off >>= 1) s += __shfl_xor_sync(0xffffffffu, s, off);
            ks[row][lane] = kv * rsqrtf(s);
            ((float*)&vs4[row][0])[lane] = vv;
        }
        __syncthreads();
#pragma unroll
        for (int r = 0; r < 32; r++) {
            float kk = ks[r][d];
            float4 vv = vs4[r][e4];
            acc[0] += kk * vv.x; acc[1] += kk * vv.y;
            acc[2] += kk * vv.z; acc[3] += kk * vv.w;
        }
        __syncthreads();
    }
    float* ap = g_attn + nh * (DD * DD) + d * DD + e4 * 4;
    atomicAdd(ap + 0, acc[0]); atomicAdd(ap + 1, acc[1]);
    atomicAdd(ap + 2, acc[2]); atomicAdd(ap + 3, acc[3]);
}

// ---------------------------------------------------------------------------
// Fused: qnorm -> q@attn*(1/pi) + 0.5v -> l2norm -> + dconv(v) -> g_mid[N,L,C]
// One warp per token row; 8 rows per block; block fixed (n,h).
// ---------------------------------------------------------------------------
__global__ __launch_bounds__(256) void k_out(const float* __restrict__ wdc) {
    __shared__ float attn_s[32][32];
    __shared__ float ws[12];
    const int bid = blockIdx.x;
    const int nh = bid >> 9;
    const int ltile = bid & 511;
    const int n = nh >> 3, hh = nh & 7;
    const int tid = threadIdx.x;
    const int wid = tid >> 5, lane = tid & 31;

    const float* ap = g_attn + nh * 1024;
    const float INV_PI = 0.3183098861837907f;
    for (int i = tid; i < 1024; i += 256) ((float*)attn_s)[i] = ap[i] * INV_PI;
    if (tid < 9) ws[tid] = wdc[hh * 9 + tid];
    __syncthreads();

    const int l = ltile * 8 + wid;
    const float* base = g_qkv + (size_t)(n * LL + l) * J3 + hh * DD;

    float qv = base[lane];
    float s = qv * qv;
#pragma unroll
    for (int off = 16; off; off >>= 1) s += __shfl_xor_sync(0xffffffffu, s, off);
    float qn = qv * rsqrtf(s);

    float o = 0.f;
#pragma unroll
    for (int dd = 0; dd < 32; dd++)
        o = fmaf(__shfl_sync(0xffffffffu, qn, dd), attn_s[dd][lane], o);

    float v = base[2 * CC + lane];
    o = fmaf(0.5f, v, o);

    float s2 = o * o;
#pragma unroll
    for (int off = 16; off; off >>= 1) s2 += __shfl_xor_sync(0xffffffffu, s2, off);
    o *= rsqrtf(s2);

    float dc = 0.f;
#pragma unroll
    for (int t = 0; t < 9; t++) {
        int lt = l + t - 4;
        if ((unsigned)lt < (unsigned)LL)
            dc = fmaf(ws[t], g_qkv[(size_t)(n * LL + lt) * J3 + 2 * CC + hh * DD + lane], dc);
    }
    o += dc;
    g_mid[(size_t)(n * LL + l) * CC + hh * DD + lane] = o;
}

// ---------------------------------------------------------------------------
// Proj GEMM with transposed (NCHW) write:
//   out[n, j, l] = sum_c mid[m, c] * Wp[j, c] + bp[j]
// thread tx -> m(l) fast (coalesced stores), ty -> j.
// ---------------------------------------------------------------------------
__global__ __launch_bounds__(256) void k_proj(const float* __restrict__ W,
                                               const float* __restrict__ bias,
                                               float* __restrict__ out) {
    __shared__ float As[16][64];   // As[kk][i(m)]
    __shared__ float Bs[16][64];   // Bs[kk][j]
    const int j0 = blockIdx.x * 64;          // 0..192
    const int m0 = blockIdx.y * 64;
    const int n = m0 >> 12;
    const int l0 = m0 & 4095;
    const int tid = threadIdx.x;
    const int tx = tid & 15, ty = tid >> 4;

    float acc[4][4] = {};   // acc[jj][ii]
    for (int k0 = 0; k0 < CC; k0 += 16) {
        {   // A: mid[(m0+i)*256 + k0+kkb..], transpose into As
            int i = tid >> 2, kkb = (tid & 3) * 4;
            float4 va = *(const float4*)(g_mid + (size_t)(m0 + i) * CC + k0 + kkb);
            As[kkb + 0][i] = va.x; As[kkb + 1][i] = va.y;
            As[kkb + 2][i] = va.z; As[kkb + 3][i] = va.w;
        }
        {   // B
            int j = tid >> 2, kkb = (tid & 3) * 4;
            float4 vb = *(const float4*)(W + (size_t)(j0 + j) * CC + k0 + kkb);
            Bs[kkb + 0][j] = vb.x; Bs[kkb + 1][j] = vb.y;
            Bs[kkb + 2][j] = vb.z; Bs[kkb + 3][j] = vb.w;
        }
        __syncthreads();
#pragma unroll
        for (int kk = 0; kk < 16; kk++) {
            float4 a = *(const float4*)&As[kk][tx * 4];
            float4 b = *(const float4*)&Bs[kk][ty * 4];
            float av[4] = {a.x, a.y, a.z, a.w};
            float bv[4] = {b.x, b.y, b.z, b.w};
#pragma unroll
            for (int jj = 0; jj < 4; jj++)
#pragma unroll
                for (int ii = 0; ii < 4; ii++) acc[jj][ii] += bv[jj] * av[ii];
        }
        __syncthreads();
    }
#pragma unroll
    for (int jj = 0; jj < 4; jj++) {
        int j = j0 + ty * 4 + jj;
        float b = bias[j];
        float4 o = make_float4(acc[jj][0] + b, acc[jj][1] + b,
                               acc[jj][2] + b, acc[jj][3] + b);
        *(float4*)(out + (size_t)(n * CC + j) * LL + l0 + tx * 4) = o;
    }
}

// ---------------------------------------------------------------------------
extern "C" void kernel_launch(void* const* d_in, const int* in_sizes, int n_in,
                              void* d_out, int out_size) {
    const float* x      = (const float*)d_in[0];
    const float* w_qkv  = (const float*)d_in[1];
    const float* b_qkv  = (const float*)d_in[2];
    const float* w_proj = (const float*)d_in[3];
    const float* b_proj = (const float*)d_in[4];
    const float* w_dc   = (const float*)d_in[5];
    float* out = (float*)d_out;
    (void)in_sizes; (void)n_in; (void)out_size;

    k_gemm_qkv<<<dim3(J3 / 64, (NB * LL) / 64), 256>>>(x, w_qkv, b_qkv);
    k_zero_attn<<<(NH * DD * DD + 255) / 256, 256>>>();
    k_attn<<<dim3(NH, SPLIT), 256>>>();
    k_out<<<NH * (LL / 8), 256>>>(w_dc);
    k_proj<<<dim3(CC / 64, (NB * LL) / 64), 256>>>(w_proj, b_proj, out);
}

// round 2
// speedup vs baseline: 1.0000x; 1.0000x over previous
#include <cuda_runtime.h>

// LinAngularAttention  fp32 baseline
// x:[8,256,64,64], w_qkv:[768,256], b_qkv:[768], w_proj:[256,256], b_proj:[256], w_dconv:[8,1,9,1]
// out:[8,256,64,64]

#define NB 8
#define CC 256
#define HH 8
#define DD 32
#define LL 4096
#define J3 768
#define NH (NB*HH)
#define SPLIT 16

__device__ float g_qkv[(size_t)NB * LL * J3];   // [N, L, 3C]  (3C order: q|k|v, each h*32+d)
__device__ float g_attn[NH * DD * DD];          // [N*H, D, D]
__device__ float g_mid[(size_t)NB * LL * CC];   // [N, L, C]

// ---------------------------------------------------------------------------
// QKV GEMM: qkv[m, j] = sum_c x[n, c, l] * Wq[j, c] + bq[j]    (m = n*L + l)
// 64x64 block tile, BK=16, 256 threads, 4x4 per thread.
// thread tx -> j (output fast dim), ty -> m.
// ---------------------------------------------------------------------------
__global__ __launch_bounds__(256) void k_gemm_qkv(const float* __restrict__ x,
                                                  const float* __restrict__ W,
                                                  const float* __restrict__ bias) {
    __shared__ float As[16][64];   // As[kk][i(m)]
    __shared__ float Bs[16][64];   // Bs[kk][j]
    const int j0 = blockIdx.x * 64;          // 0..704
    const int m0 = blockIdx.y * 64;          // 0..32704
    const int n  = m0 >> 12;
    const int l0 = m0 & 4095;
    const int tid = threadIdx.x;
    const int tx = tid & 15, ty = tid >> 4;
    const float* xb = x + (size_t)n * CC * LL;

    float acc[4][4] = {};
    for (int k0 = 0; k0 < CC; k0 += 16) {
        {   // A: As[kk][i] = x[n, k0+kk, l0+i]   (contiguous in l)
            int idx = tid * 4;
            int kk = idx >> 6, i = idx & 63;
            float4 va = *(const float4*)(xb + (size_t)(k0 + kk) * LL + l0 + i);
            *(float4*)&As[kk][i] = va;
        }
        {   // B: Bs[kk][j] = W[(j0+j)*256 + k0+kk]  (transpose during load)
            int j = tid >> 2, kkb = (tid & 3) * 4;
            float4 vb = *(const float4*)(W + (size_t)(j0 + j) * CC + k0 + kkb);
            Bs[kkb + 0][j] = vb.x; Bs[kkb + 1][j] = vb.y;
            Bs[kkb + 2][j] = vb.z; Bs[kkb + 3][j] = vb.w;
        }
        __syncthreads();
#pragma unroll
        for (int kk = 0; kk < 16; kk++) {
            float4 a = *(const float4*)&As[kk][ty * 4];
            float4 b = *(const float4*)&Bs[kk][tx * 4];
            float av[4] = {a.x, a.y, a.z, a.w};
            float bv[4] = {b.x, b.y, b.z, b.w};
#pragma unroll
            for (int i = 0; i < 4; i++)
#pragma unroll
                for (int j = 0; j < 4; j++) acc[i][j] += av[i] * bv[j];
        }
        __syncthreads();
    }
    float4 bb = *(const float4*)(bias + j0 + tx * 4);
    float bv[4] = {bb.x, bb.y, bb.z, bb.w};
#pragma unroll
    for (int i = 0; i < 4; i++) {
        int m = m0 + ty * 4 + i;
        float4 o = make_float4(acc[i][0] + bv[0], acc[i][1] + bv[1],
                               acc[i][2] + bv[2], acc[i][3] + bv[3]);
        *(float4*)(g_qkv + (size_t)m * J3 + j0 + tx * 4) = o;
    }
}

// ---------------------------------------------------------------------------
__global__ void k_zero_attn() {
    int i = blockIdx.x * 256 + threadIdx.x;
    if (i < NH * DD * DD) g_attn[i] = 0.f;
}

// attn[nh, d, e] += sum_l knorm[l,d] * v[l,e], split over L into SPLIT chunks.
__global__ __launch_bounds__(256) void k_attn() {
    __shared__ float  ks[32][32];
    __shared__ float4 vs4[32][8];
    const int nh = blockIdx.x;              // 0..63
    const int chunk = blockIdx.y;           // 0..SPLIT-1
    const int n = nh >> 3, hh = nh & 7;
    const int tid = threadIdx.x;
    const int wid = tid >> 5, lane = tid & 31;
    const int d = tid >> 3, e4 = tid & 7;   // thread owns (d, 4e) pairs
    const int lbase = chunk * (LL / SPLIT);
    const float* qb = g_qkv + (size_t)n * LL * J3;

    float acc[4] = {};
    for (int t0 = 0; t0 < LL / SPLIT; t0 += 32) {
#pragma unroll
        for (int rr = 0; rr < 4; rr++) {
            int row = wid * 4 + rr;
            const float* rowp = qb + (size_t)(lbase + t0 + row) * J3 + hh * DD;
            float kv = rowp[CC + lane];       // k
            float vv = rowp[2 * CC + lane];   // v
            float s = kv * kv;
#pragma unroll
            for (int off = 16; off; off >>= 1) s += __shfl_xor_sync(0xffffffffu, s, off);
            ks[row][lane] = kv * rsqrtf(s);
            ((float*)&vs4[row][0])[lane] = vv;
        }
        __syncthreads();
#pragma unroll
        for (int r = 0; r < 32; r++) {
            float kk = ks[r][d];
            float4 vv = vs4[r][e4];
            acc[0] += kk * vv.x; acc[1] += kk * vv.y;
            acc[2] += kk * vv.z; acc[3] += kk * vv.w;
        }
        __syncthreads();
    }
    float* ap = g_attn + nh * (DD * DD) + d * DD + e4 * 4;
    atomicAdd(ap + 0, acc[0]); atomicAdd(ap + 1, acc[1]);
    atomicAdd(ap + 2, acc[2]); atomicAdd(ap + 3, acc[3]);
}

// ---------------------------------------------------------------------------
// Fused: qnorm -> q@attn*(1/pi) + 0.5v -> l2norm -> + dconv(v) -> g_mid[N,L,C]
// One warp per token row; 8 rows per block; block fixed (n,h).
// ---------------------------------------------------------------------------
__global__ __launch_bounds__(256) void k_out(const float* __restrict__ wdc) {
    __shared__ float attn_s[32][32];
    __shared__ float ws[12];
    const int bid = blockIdx.x;
    const int nh = bid >> 9;
    const int ltile = bid & 511;
    const int n = nh >> 3, hh = nh & 7;
    const int tid = threadIdx.x;
    const int wid = tid >> 5, lane = tid & 31;

    const float* ap = g_attn + nh * 1024;
    const float INV_PI = 0.3183098861837907f;
    for (int i = tid; i < 1024; i += 256) ((float*)attn_s)[i] = ap[i] * INV_PI;
    if (tid < 9) ws[tid] = wdc[hh * 9 + tid];
    __syncthreads();

    const int l = ltile * 8 + wid;
    const float* base = g_qkv + (size_t)(n * LL + l) * J3 + hh * DD;

    float qv = base[lane];
    float s = qv * qv;
#pragma unroll
    for (int off = 16; off; off >>= 1) s += __shfl_xor_sync(0xffffffffu, s, off);
    float qn = qv * rsqrtf(s);

    float o = 0.f;
#pragma unroll
    for (int dd = 0; dd < 32; dd++)
        o = fmaf(__shfl_sync(0xffffffffu, qn, dd), attn_s[dd][lane], o);

    float v = base[2 * CC + lane];
    o = fmaf(0.5f, v, o);

    float s2 = o * o;
#pragma unroll
    for (int off = 16; off; off >>= 1) s2 += __shfl_xor_sync(0xffffffffu, s2, off);
    o *= rsqrtf(s2);

    float dc = 0.f;
#pragma unroll
    for (int t = 0; t < 9; t++) {
        int lt = l + t - 4;
        if ((unsigned)lt < (unsigned)LL)
            dc = fmaf(ws[t], g_qkv[(size_t)(n * LL + lt) * J3 + 2 * CC + hh * DD + lane], dc);
    }
    o += dc;
    g_mid[(size_t)(n * LL + l) * CC + hh * DD + lane] = o;
}

// ---------------------------------------------------------------------------
// Proj GEMM with transposed (NCHW) write:
//   out[n, j, l] = sum_c mid[m, c] * Wp[j, c] + bp[j]
// thread tx -> m(l) fast (coalesced stores), ty -> j.
// ---------------------------------------------------------------------------
__global__ __launch_bounds__(256) void k_proj(const float* __restrict__ W,
                                               const float* __restrict__ bias,
                                               float* __restrict__ out) {
    __shared__ float As[16][64];   // As[kk][i(m)]
    __shared__ float Bs[16][64];   // Bs[kk][j]
    const int j0 = blockIdx.x * 64;          // 0..192
    const int m0 = blockIdx.y * 64;
    const int n = m0 >> 12;
    const int l0 = m0 & 4095;
    const int tid = threadIdx.x;
    const int tx = tid & 15, ty = tid >> 4;

    float acc[4][4] = {};   // acc[jj][ii]
    for (int k0 = 0; k0 < CC; k0 += 16) {
        {   // A: mid[(m0+i)*256 + k0+kkb..], transpose into As
            int i = tid >> 2, kkb = (tid & 3) * 4;
            float4 va = *(const float4*)(g_mid + (size_t)(m0 + i) * CC + k0 + kkb);
            As[kkb + 0][i] = va.x; As[kkb + 1][i] = va.y;
            As[kkb + 2][i] = va.z; As[kkb + 3][i] = va.w;
        }
        {   // B
            int j = tid >> 2, kkb = (tid & 3) * 4;
            float4 vb = *(const float4*)(W + (size_t)(j0 + j) * CC + k0 + kkb);
            Bs[kkb + 0][j] = vb.x; Bs[kkb + 1][j] = vb.y;
            Bs[kkb + 2][j] = vb.z; Bs[kkb + 3][j] = vb.w;
        }
        __syncthreads();
#pragma unroll
        for (int kk = 0; kk < 16; kk++) {
            float4 a = *(const float4*)&As[kk][tx * 4];
            float4 b = *(const float4*)&Bs[kk][ty * 4];
            float av[4] = {a.x, a.y, a.z, a.w};
            float bv[4] = {b.x, b.y, b.z, b.w};
#pragma unroll
            for (int jj = 0; jj < 4; jj++)
#pragma unroll
                for (int ii = 0; ii < 4; ii++) acc[jj][ii] += bv[jj] * av[ii];
        }
        __syncthreads();
    }
#pragma unroll
    for (int jj = 0; jj < 4; jj++) {
        int j = j0 + ty * 4 + jj;
        float b = bias[j];
        float4 o = make_float4(acc[jj][0] + b, acc[jj][1] + b,
                               acc[jj][2] + b, acc[jj][3] + b);
        *(float4*)(out + (size_t)(n * CC + j) * LL + l0 + tx * 4) = o;
    }
}

// ---------------------------------------------------------------------------
extern "C" void kernel_launch(void* const* d_in, const int* in_sizes, int n_in,
                              void* d_out, int out_size) {
    const float* x      = (const float*)d_in[0];
    const float* w_qkv  = (const float*)d_in[1];
    const float* b_qkv  = (const float*)d_in[2];
    const float* w_proj = (const float*)d_in[3];
    const float* b_proj = (const float*)d_in[4];
    const float* w_dc   = (const float*)d_in[5];
    float* out = (float*)d_out;
    (void)in_sizes; (void)n_in; (void)out_size;

    k_gemm_qkv<<<dim3(J3 / 64, (NB * LL) / 64), 256>>>(x, w_qkv, b_qkv);
    k_zero_attn<<<(NH * DD * DD + 255) / 256, 256>>>();
    k_attn<<<dim3(NH, SPLIT), 256>>>();
    k_out<<<NH * (LL / 8), 256>>>(w_dc);
    k_proj<<<dim3(CC / 64, (NB * LL) / 64), 256>>>(w_proj, b_proj, out);
}

// round 3
// speedup vs baseline: 1.1660x; 1.1660x over previous
#include <cuda_runtime.h>

// LinAngularAttention fp32 — round 2: 128x128x8 SGEMM (8x8/thread), tiled k_out
// x:[8,256,64,64], w_qkv:[768,256], b_qkv:[768], w_proj:[256,256], b_proj:[256], w_dconv:[8,1,9,1]

#define NB 8
#define CC 256
#define HH 8
#define DD 32
#define LL 4096
#define J3 768
#define NH (NB*HH)
#define SPLIT 16

__device__ float g_qkv[(size_t)NB * LL * J3];   // [N, L, 3C] (q|k|v, each h*32+d)
__device__ float g_attn[NH * DD * DD];          // [N*H, D, D]
__device__ float g_mid[(size_t)NB * LL * CC];   // [N, L, C]

// ---------------------------------------------------------------------------
// QKV GEMM: qkv[m, j] = sum_c x[n, c, l] * Wq[j, c] + bq[j]   (m = n*L + l)
// 128x128 tile, BK=8, 256 threads, 8x8 per thread. tx->j, ty->m.
// ---------------------------------------------------------------------------
__global__ __launch_bounds__(256) void k_gemm_qkv(const float* __restrict__ x,
                                                  const float* __restrict__ W,
                                                  const float* __restrict__ bias) {
    __shared__ float As[8][128];
    __shared__ float Bs[8][132];   // padded: transpose-store conflict-free, rows 16B-aligned
    const int j0 = blockIdx.x * 128;
    const int m0 = blockIdx.y * 128;
    const int n  = m0 >> 12;
    const int l0 = m0 & 4095;
    const int tid = threadIdx.x;
    const int tx = tid & 15, ty = tid >> 4;
    const float* xb = x + (size_t)n * CC * LL;

    const int kkA = tid >> 5, iA = (tid & 31) * 4;   // A loader coords
    const int jB  = tid >> 1, kB = (tid & 1) * 4;    // B loader coords

    float acc[8][8] = {};
    float4 va = *(const float4*)(xb + (size_t)kkA * LL + l0 + iA);
    float4 vb = *(const float4*)(W + (size_t)(j0 + jB) * CC + kB);

    for (int k0 = 0; k0 < CC; k0 += 8) {
        *(float4*)&As[kkA][iA] = va;
        Bs[kB + 0][jB] = vb.x; Bs[kB + 1][jB] = vb.y;
        Bs[kB + 2][jB] = vb.z; Bs[kB + 3][jB] = vb.w;
        __syncthreads();
        if (k0 + 8 < CC) {
            va = *(const float4*)(xb + (size_t)(k0 + 8 + kkA) * LL + l0 + iA);
            vb = *(const float4*)(W + (size_t)(j0 + jB) * CC + k0 + 8 + kB);
        }
#pragma unroll
        for (int kk = 0; kk < 8; kk++) {
            float4 a0 = *(const float4*)&As[kk][ty * 8];
            float4 a1 = *(const float4*)&As[kk][ty * 8 + 4];
            float4 b0 = *(const float4*)&Bs[kk][tx * 8];
            float4 b1 = *(const float4*)&Bs[kk][tx * 8 + 4];
            float av[8] = {a0.x, a0.y, a0.z, a0.w, a1.x, a1.y, a1.z, a1.w};
            float bv[8] = {b0.x, b0.y, b0.z, b0.w, b1.x, b1.y, b1.z, b1.w};
#pragma unroll
            for (int i = 0; i < 8; i++)
#pragma unroll
                for (int j = 0; j < 8; j++) acc[i][j] = fmaf(av[i], bv[j], acc[i][j]);
        }
        __syncthreads();
    }
    float4 bb0 = *(const float4*)(bias + j0 + tx * 8);
    float4 bb1 = *(const float4*)(bias + j0 + tx * 8 + 4);
    float bv[8] = {bb0.x, bb0.y, bb0.z, bb0.w, bb1.x, bb1.y, bb1.z, bb1.w};
#pragma unroll
    for (int i = 0; i < 8; i++) {
        int m = m0 + ty * 8 + i;
        float* op = g_qkv + (size_t)m * J3 + j0 + tx * 8;
        *(float4*)op = make_float4(acc[i][0] + bv[0], acc[i][1] + bv[1],
                                   acc[i][2] + bv[2], acc[i][3] + bv[3]);
        *(float4*)(op + 4) = make_float4(acc[i][4] + bv[4], acc[i][5] + bv[5],
                                         acc[i][6] + bv[6], acc[i][7] + bv[7]);
    }
}

// ---------------------------------------------------------------------------
__global__ void k_zero_attn() {
    int i = blockIdx.x * 256 + threadIdx.x;
    if (i < NH * DD * DD) g_attn[i] = 0.f;
}

// attn[nh, d, e] += sum_l knorm[l,d] * v[l,e], L split into SPLIT chunks.
__global__ __launch_bounds__(256) void k_attn() {
    __shared__ float  ks[32][32];
    __shared__ float4 vs4[32][8];
    const int nh = blockIdx.x;
    const int chunk = blockIdx.y;
    const int n = nh >> 3, hh = nh & 7;
    const int tid = threadIdx.x;
    const int wid = tid >> 5, lane = tid & 31;
    const int d = tid >> 3, e4 = tid & 7;
    const int lbase = chunk * (LL / SPLIT);
    const float* qb = g_qkv + (size_t)n * LL * J3;

    float acc[4] = {};
    for (int t0 = 0; t0 < LL / SPLIT; t0 += 32) {
#pragma unroll
        for (int rr = 0; rr < 4; rr++) {
            int row = wid * 4 + rr;
            const float* rowp = qb + (size_t)(lbase + t0 + row) * J3 + hh * DD;
            float kv = rowp[CC + lane];
            float vv = rowp[2 * CC + lane];
            float s = kv * kv;
#pragma unroll
            for (int off = 16; off; off >>= 1) s += __shfl_xor_sync(0xffffffffu, s, off);
            ks[row][lane] = kv * rsqrtf(s);
            ((float*)&vs4[row][0])[lane] = vv;
        }
        __syncthreads();
#pragma unroll
        for (int r = 0; r < 32; r++) {
            float kk = ks[r][d];
            float4 vv = vs4[r][e4];
            acc[0] += kk * vv.x; acc[1] += kk * vv.y;
            acc[2] += kk * vv.z; acc[3] += kk * vv.w;
        }
        __syncthreads();
    }
    float* ap = g_attn + nh * (DD * DD) + d * DD + e4 * 4;
    atomicAdd(ap + 0, acc[0]); atomicAdd(ap + 1, acc[1]);
    atomicAdd(ap + 2, acc[2]); atomicAdd(ap + 3, acc[3]);
}

// ---------------------------------------------------------------------------
// Fused epilogue: qnorm -> (1/pi) q@attn + 0.5v -> l2norm -> + dconv(v).
// Block = (n,h) x 128-token tile; v staged in smem with +-4 halo.
// ---------------------------------------------------------------------------
#define TOK 128
__global__ __launch_bounds__(256) void k_out(const float* __restrict__ wdc) {
    __shared__ float attn_s[32][32];
    __shared__ float v_s[TOK + 8][32];
    __shared__ float ws[12];
    const int bid = blockIdx.x;
    const int nh = bid >> 5;               // 64 (n,h) values
    const int ltile = bid & 31;            // 32 tiles of 128 tokens
    const int n = nh >> 3, hh = nh & 7;
    const int tid = threadIdx.x;
    const int wid = tid >> 5, lane = tid & 31;
    const int l0 = ltile * TOK;

    const float INV_PI = 0.3183098861837907f;
    const float* ap = g_attn + nh * 1024;
    for (int i = tid; i < 1024; i += 256) ((float*)attn_s)[i] = ap[i] * INV_PI;
    if (tid < 9) ws[tid] = wdc[hh * 9 + tid];

    // stage v rows l0-4 .. l0+TOK+3 (zero-padded at sequence ends)
    const float* vbase = g_qkv + ((size_t)n * LL) * J3 + 2 * CC + hh * DD;
    for (int i = tid; i < (TOK + 8) * 8; i += 256) {
        int r = i >> 3, c4 = (i & 7) * 4;
        int l = l0 - 4 + r;
        float4 v4 = make_float4(0.f, 0.f, 0.f, 0.f);
        if ((unsigned)l < (unsigned)LL)
            v4 = *(const float4*)(vbase + (size_t)l * J3 + c4);
        *(float4*)&v_s[r][c4] = v4;
    }
    __syncthreads();

    const float* qbase = g_qkv + ((size_t)n * LL) * J3 + hh * DD;
    float* mbase = g_mid + ((size_t)n * LL) * CC + hh * DD;

    for (int tt = wid; tt < TOK; tt += 8) {
        int l = l0 + tt;
        float qv = qbase[(size_t)l * J3 + lane];
        float s = qv * qv;
#pragma unroll
        for (int off = 16; off; off >>= 1) s += __shfl_xor_sync(0xffffffffu, s, off);
        float qn = qv * rsqrtf(s);

        float o = 0.f;
#pragma unroll
        for (int dd = 0; dd < 32; dd++)
            o = fmaf(__shfl_sync(0xffffffffu, qn, dd), attn_s[dd][lane], o);

        float v = v_s[tt + 4][lane];
        o = fmaf(0.5f, v, o);

        float s2 = o * o;
#pragma unroll
        for (int off = 16; off; off >>= 1) s2 += __shfl_xor_sync(0xffffffffu, s2, off);
        o *= rsqrtf(s2);

        float dc = 0.f;
#pragma unroll
        for (int t = 0; t < 9; t++)
            dc = fmaf(ws[t], v_s[tt + t][lane], dc);

        mbase[(size_t)l * CC + lane] = o + dc;
    }
}

// ---------------------------------------------------------------------------
// Proj GEMM, transposed (NCHW) write: out[n, j, l] = sum_c mid[m, c]*Wp[j, c] + bp[j]
// 128x128 tile, 8x8/thread. tx->m(l) fast for coalesced stores, ty->j.
// ---------------------------------------------------------------------------
__global__ __launch_bounds__(256) void k_proj(const float* __restrict__ W,
                                               const float* __restrict__ bias,
                                               float* __restrict__ out) {
    __shared__ float As[8][132];   // As[kk][i(m)], padded
    __shared__ float Bs[8][132];   // Bs[kk][j], padded
    const int j0 = blockIdx.x * 128;   // 0..128
    const int m0 = blockIdx.y * 128;
    const int n = m0 >> 12;
    const int l0 = m0 & 4095;
    const int tid = threadIdx.x;
    const int tx = tid & 15, ty = tid >> 4;

    const int iA = tid >> 1, kA = (tid & 1) * 4;
    const int jB = tid >> 1, kB = (tid & 1) * 4;

    float acc[8][8] = {};   // acc[jj][ii]
    float4 va = *(const float4*)(g_mid + (size_t)(m0 + iA) * CC + kA);
    float4 vb = *(const float4*)(W + (size_t)(j0 + jB) * CC + kB);

    for (int k0 = 0; k0 < CC; k0 += 8) {
        As[kA + 0][iA] = va.x; As[kA + 1][iA] = va.y;
        As[kA + 2][iA] = va.z; As[kA + 3][iA] = va.w;
        Bs[kB + 0][jB] = vb.x; Bs[kB + 1][jB] = vb.y;
        Bs[kB + 2][jB] = vb.z; Bs[kB + 3][jB] = vb.w;
        __syncthreads();
        if (k0 + 8 < CC) {
            va = *(const float4*)(g_mid + (size_t)(m0 + iA) * CC + k0 + 8 + kA);
            vb = *(const float4*)(W + (size_t)(j0 + jB) * CC + k0 + 8 + kB);
        }
#pragma unroll
        for (int kk = 0; kk < 8; kk++) {
            float4 a0 = *(const float4*)&As[kk][tx * 8];
            float4 a1 = *(const float4*)&As[kk][tx * 8 + 4];
            float4 b0 = *(const float4*)&Bs[kk][ty * 8];
            float4 b1 = *(const float4*)&Bs[kk][ty * 8 + 4];
            float av[8] = {a0.x, a0.y, a0.z, a0.w, a1.x, a1.y, a1.z, a1.w};
            float bv[8] = {b0.x, b0.y, b0.z, b0.w, b1.x, b1.y, b1.z, b1.w};
#pragma unroll
            for (int jj = 0; jj < 8; jj++)
#pragma unroll
                for (int ii = 0; ii < 8; ii++) acc[jj][ii] = fmaf(bv[jj], av[ii], acc[jj][ii]);
        }
        __syncthreads();
    }
#pragma unroll
    for (int jj = 0; jj < 8; jj++) {
        int j = j0 + ty * 8 + jj;
        float b = bias[j];
        float* op = out + (size_t)(n * CC + j) * LL + l0 + tx * 8;
        *(float4*)op = make_float4(acc[jj][0] + b, acc[jj][1] + b,
                                   acc[jj][2] + b, acc[jj][3] + b);
        *(float4*)(op + 4) = make_float4(acc[jj][4] + b, acc[jj][5] + b,
                                         acc[jj][6] + b, acc[jj][7] + b);
    }
}

// ---------------------------------------------------------------------------
extern "C" void kernel_launch(void* const* d_in, const int* in_sizes, int n_in,
                              void* d_out, int out_size) {
    const float* x      = (const float*)d_in[0];
    const float* w_qkv  = (const float*)d_in[1];
    const float* b_qkv  = (const float*)d_in[2];
    const float* w_proj = (const float*)d_in[3];
    const float* b_proj = (const float*)d_in[4];
    const float* w_dc   = (const float*)d_in[5];
    float* out = (float*)d_out;
    (void)in_sizes; (void)n_in; (void)out_size;

    k_gemm_qkv<<<dim3(J3 / 128, (NB * LL) / 128), 256>>>(x, w_qkv, b_qkv);
    k_zero_attn<<<(NH * DD * DD + 255) / 256, 256>>>();
    k_attn<<<dim3(NH, SPLIT), 256>>>();
    k_out<<<NH * (LL / TOK), 256>>>(w_dc);
    k_proj<<<dim3(CC / 128, (NB * LL) / 128), 256>>>(w_proj, b_proj, out);
}

// round 4
// speedup vs baseline: 1.2333x; 1.0577x over previous
#include <cuda_runtime.h>

// LinAngularAttention fp32 — round 3: prenormalized q/k in QKV epilogue,
// shfl-free thread-per-token k_out, copy-only k_attn staging.

#define NB 8
#define CC 256
#define HH 8
#define DD 32
#define LL 4096
#define J3 768
#define NH (NB*HH)
#define SPLIT 16

__device__ float g_qkv[(size_t)NB * LL * J3];   // [N, L, 3C]; q,k stored L2-NORMALIZED
__device__ float g_attn[NH * DD * DD];          // [N*H, D, D]
__device__ float g_mid[(size_t)NB * LL * CC];   // [N, L, C]

// ---------------------------------------------------------------------------
// QKV GEMM + fused q/k l2-normalization in epilogue.
// qkv[m, j] = sum_c x[n, c, l] * Wq[j, c] + bq[j]; then rows of q,k normalized
// per head (32 dims = one tx-group of 4 threads x 8 cols).
// ---------------------------------------------------------------------------
__global__ __launch_bounds__(256) void k_gemm_qkv(const float* __restrict__ x,
                                                  const float* __restrict__ W,
                                                  const float* __restrict__ bias) {
    __shared__ float As[8][128];
    __shared__ float Bs[8][132];
    const int j0 = blockIdx.x * 128;
    const int m0 = blockIdx.y * 128;
    const int n  = m0 >> 12;
    const int l0 = m0 & 4095;
    const int tid = threadIdx.x;
    const int tx = tid & 15, ty = tid >> 4;
    const float* xb = x + (size_t)n * CC * LL;

    const int kkA = tid >> 5, iA = (tid & 31) * 4;
    const int jB  = tid >> 1, kB = (tid & 1) * 4;

    float acc[8][8] = {};
    float4 va = *(const float4*)(xb + (size_t)kkA * LL + l0 + iA);
    float4 vb = *(const float4*)(W + (size_t)(j0 + jB) * CC + kB);

    for (int k0 = 0; k0 < CC; k0 += 8) {
        *(float4*)&As[kkA][iA] = va;
        Bs[kB + 0][jB] = vb.x; Bs[kB + 1][jB] = vb.y;
        Bs[kB + 2][jB] = vb.z; Bs[kB + 3][jB] = vb.w;
        __syncthreads();
        if (k0 + 8 < CC) {
            va = *(const float4*)(xb + (size_t)(k0 + 8 + kkA) * LL + l0 + iA);
            vb = *(const float4*)(W + (size_t)(j0 + jB) * CC + k0 + 8 + kB);
        }
#pragma unroll
        for (int kk = 0; kk < 8; kk++) {
            float4 a0 = *(const float4*)&As[kk][ty * 8];
            float4 a1 = *(const float4*)&As[kk][ty * 8 + 4];
            float4 b0 = *(const float4*)&Bs[kk][tx * 8];
            float4 b1 = *(const float4*)&Bs[kk][tx * 8 + 4];
            float av[8] = {a0.x, a0.y, a0.z, a0.w, a1.x, a1.y, a1.z, a1.w};
            float bv[8] = {b0.x, b0.y, b0.z, b0.w, b1.x, b1.y, b1.z, b1.w};
#pragma unroll
            for (int i = 0; i < 8; i++)
#pragma unroll
                for (int j = 0; j < 8; j++) acc[i][j] = fmaf(av[i], bv[j], acc[i][j]);
        }
        __syncthreads();
    }
    // bias
    float4 bb0 = *(const float4*)(bias + j0 + tx * 8);
    float4 bb1 = *(const float4*)(bias + j0 + tx * 8 + 4);
    float bv[8] = {bb0.x, bb0.y, bb0.z, bb0.w, bb1.x, bb1.y, bb1.z, bb1.w};
#pragma unroll
    for (int i = 0; i < 8; i++)
#pragma unroll
        for (int j = 0; j < 8; j++) acc[i][j] += bv[j];

    // l2-normalize q,k rows per head (tiles with j0 < 512). Head spans the
    // tx-group of 4 threads (lane bits 0,1).
    if (j0 < 512) {
#pragma unroll
        for (int i = 0; i < 8; i++) {
            float s = 0.f;
#pragma unroll
            for (int j = 0; j < 8; j++) s = fmaf(acc[i][j], acc[i][j], s);
            s += __shfl_xor_sync(0xffffffffu, s, 1);
            s += __shfl_xor_sync(0xffffffffu, s, 2);
            float rn = rsqrtf(s);
#pragma unroll
            for (int j = 0; j < 8; j++) acc[i][j] *= rn;
        }
    }
#pragma unroll
    for (int i = 0; i < 8; i++) {
        int m = m0 + ty * 8 + i;
        float* op = g_qkv + (size_t)m * J3 + j0 + tx * 8;
        *(float4*)op = make_float4(acc[i][0], acc[i][1], acc[i][2], acc[i][3]);
        *(float4*)(op + 4) = make_float4(acc[i][4], acc[i][5], acc[i][6], acc[i][7]);
    }
}

// ---------------------------------------------------------------------------
__global__ void k_zero_attn() {
    int i = blockIdx.x * 256 + threadIdx.x;
    if (i < NH * DD * DD) g_attn[i] = 0.f;
}

// attn[nh, d, e] += sum_l knorm[l,d] * v[l,e]; k already normalized.
__global__ __launch_bounds__(256) void k_attn() {
    __shared__ float ks[32][32];
    __shared__ float vs[32][32];
    const int nh = blockIdx.x;
    const int chunk = blockIdx.y;
    const int n = nh >> 3, hh = nh & 7;
    const int tid = threadIdx.x;
    const int d = tid >> 3, e4 = tid & 7;
    const int lbase = chunk * (LL / SPLIT);
    const float* base = g_qkv + (size_t)n * LL * J3 + hh * DD;

    const int r = tid >> 3, c4 = (tid & 7) * 4;
    float acc[4] = {};
    for (int t0 = 0; t0 < LL / SPLIT; t0 += 32) {
        const float* rp = base + (size_t)(lbase + t0 + r) * J3;
        *(float4*)&ks[r][c4] = *(const float4*)(rp + CC + c4);
        *(float4*)&vs[r][c4] = *(const float4*)(rp + 2 * CC + c4);
        __syncthreads();
#pragma unroll
        for (int rr = 0; rr < 32; rr++) {
            float kk = ks[rr][d];
            float4 vv = *(const float4*)&vs[rr][e4 * 4];
            acc[0] = fmaf(kk, vv.x, acc[0]);
            acc[1] = fmaf(kk, vv.y, acc[1]);
            acc[2] = fmaf(kk, vv.z, acc[2]);
            acc[3] = fmaf(kk, vv.w, acc[3]);
        }
        __syncthreads();
    }
    float* ap = g_attn + nh * (DD * DD) + d * DD + e4 * 4;
    atomicAdd(ap + 0, acc[0]); atomicAdd(ap + 1, acc[1]);
    atomicAdd(ap + 2, acc[2]); atomicAdd(ap + 3, acc[3]);
}

// ---------------------------------------------------------------------------
// Fused epilogue, thread-per-token, no shuffles:
//   o = (1/pi) qn@attn + 0.5 v ; o /= |o| ; o += dconv(v) ; -> g_mid
// q_s: stride-33 (scalar reads conflict-free). v_s: XOR-swizzled float4 rows.
// ---------------------------------------------------------------------------
#define TOK 128
__global__ __launch_bounds__(128) void k_out(const float* __restrict__ wdc) {
    __shared__ float att[32][32];          // prescaled by 1/pi, broadcast reads
    __shared__ float q_s[TOK][33];
    __shared__ float v_s[TOK + 8][32];     // col4 index XOR (row&7)
    __shared__ float ws[9];
    const int bid = blockIdx.x;
    const int nh = bid >> 5;
    const int ltile = bid & 31;
    const int n = nh >> 3, hh = nh & 7;
    const int tid = threadIdx.x;
    const int l0 = ltile * TOK;

    const float INV_PI = 0.3183098861837907f;
    for (int i = tid; i < 1024; i += 128) ((float*)att)[i] = g_attn[nh * 1024 + i] * INV_PI;
    if (tid < 9) ws[tid] = wdc[hh * 9 + tid];

    const float* qb = g_qkv + (size_t)n * LL * J3 + hh * DD;

    // stage q (normalized already): scalar stores into stride-33 rows
    for (int i = tid; i < TOK * 8; i += 128) {
        int r = i >> 3, c4 = (i & 7) * 4;
        float4 v4 = *(const float4*)(qb + (size_t)(l0 + r) * J3 + c4);
        q_s[r][c4 + 0] = v4.x; q_s[r][c4 + 1] = v4.y;
        q_s[r][c4 + 2] = v4.z; q_s[r][c4 + 3] = v4.w;
    }
    // stage v rows l0-4 .. l0+TOK+3, XOR swizzle
    for (int i = tid; i < (TOK + 8) * 8; i += 128) {
        int r = i >> 3, c4 = i & 7;
        int l = l0 - 4 + r;
        float4 v4 = make_float4(0.f, 0.f, 0.f, 0.f);
        if ((unsigned)l < (unsigned)LL)
            v4 = *(const float4*)(qb + (size_t)l * J3 + 2 * CC + c4 * 4);
        *(float4*)&v_s[r][(c4 ^ (r & 7)) * 4] = v4;
    }
    __syncthreads();

    const int t = tid;
    const int l = l0 + t;

    float4 o[8];
    {   // o = 0.5 * v
        int r = t + 4;
#pragma unroll
        for (int e4 = 0; e4 < 8; e4++) {
            float4 vv = *(const float4*)&v_s[r][(e4 ^ (r & 7)) * 4];
            o[e4] = make_float4(0.5f * vv.x, 0.5f * vv.y, 0.5f * vv.z, 0.5f * vv.w);
        }
    }
#pragma unroll 4
    for (int d = 0; d < 32; d++) {
        float qd = q_s[t][d];
#pragma unroll
        for (int e4 = 0; e4 < 8; e4++) {
            float4 a = *(const float4*)&att[d][e4 * 4];
            o[e4].x = fmaf(qd, a.x, o[e4].x);
            o[e4].y = fmaf(qd, a.y, o[e4].y);
            o[e4].z = fmaf(qd, a.z, o[e4].z);
            o[e4].w = fmaf(qd, a.w, o[e4].w);
        }
    }
    // l2 norm (thread-local)
    float s = 0.f;
#pragma unroll
    for (int e4 = 0; e4 < 8; e4++)
        s += o[e4].x * o[e4].x + o[e4].y * o[e4].y + o[e4].z * o[e4].z + o[e4].w * o[e4].w;
    float rn = rsqrtf(s);
#pragma unroll
    for (int e4 = 0; e4 < 8; e4++) {
        o[e4].x *= rn; o[e4].y *= rn; o[e4].z *= rn; o[e4].w *= rn;
    }
    // + dconv(v)
#pragma unroll
    for (int tap = 0; tap < 9; tap++) {
        float wt = ws[tap];
        int r = t + tap;
#pragma unroll
        for (int e4 = 0; e4 < 8; e4++) {
            float4 vv = *(const float4*)&v_s[r][(e4 ^ (r & 7)) * 4];
            o[e4].x = fmaf(wt, vv.x, o[e4].x);
            o[e4].y = fmaf(wt, vv.y, o[e4].y);
            o[e4].z = fmaf(wt, vv.z, o[e4].z);
            o[e4].w = fmaf(wt, vv.w, o[e4].w);
        }
    }
    float* mp = g_mid + (size_t)(n * LL + l) * CC + hh * DD;
#pragma unroll
    for (int e4 = 0; e4 < 8; e4++) *(float4*)(mp + e4 * 4) = o[e4];
}

// ---------------------------------------------------------------------------
// Proj GEMM, transposed (NCHW) write.
// ---------------------------------------------------------------------------
__global__ __launch_bounds__(256) void k_proj(const float* __restrict__ W,
                                               const float* __restrict__ bias,
                                               float* __restrict__ out) {
    __shared__ float As[8][132];
    __shared__ float Bs[8][132];
    const int j0 = blockIdx.x * 128;
    const int m0 = blockIdx.y * 128;
    const int n = m0 >> 12;
    const int l0 = m0 & 4095;
    const int tid = threadIdx.x;
    const int tx = tid & 15, ty = tid >> 4;

    const int iA = tid >> 1, kA = (tid & 1) * 4;
    const int jB = tid >> 1, kB = (tid & 1) * 4;

    float acc[8][8] = {};
    float4 va = *(const float4*)(g_mid + (size_t)(m0 + iA) * CC + kA);
    float4 vb = *(const float4*)(W + (size_t)(j0 + jB) * CC + kB);

    for (int k0 = 0; k0 < CC; k0 += 8) {
        As[kA + 0][iA] = va.x; As[kA + 1][iA] = va.y;
        As[kA + 2][iA] = va.z; As[kA + 3][iA] = va.w;
        Bs[kB + 0][jB] = vb.x; Bs[kB + 1][jB] = vb.y;
        Bs[kB + 2][jB] = vb.z; Bs[kB + 3][jB] = vb.w;
        __syncthreads();
        if (k0 + 8 < CC) {
            va = *(const float4*)(g_mid + (size_t)(m0 + iA) * CC + k0 + 8 + kA);
            vb = *(const float4*)(W + (size_t)(j0 + jB) * CC + k0 + 8 + kB);
        }
#pragma unroll
        for (int kk = 0; kk < 8; kk++) {
            float4 a0 = *(const float4*)&As[kk][tx * 8];
            float4 a1 = *(const float4*)&As[kk][tx * 8 + 4];
            float4 b0 = *(const float4*)&Bs[kk][ty * 8];
            float4 b1 = *(const float4*)&Bs[kk][ty * 8 + 4];
            float av[8] = {a0.x, a0.y, a0.z, a0.w, a1.x, a1.y, a1.z, a1.w};
            float bv[8] = {b0.x, b0.y, b0.z, b0.w, b1.x, b1.y, b1.z, b1.w};
#pragma unroll
            for (int jj = 0; jj < 8; jj++)
#pragma unroll
                for (int ii = 0; ii < 8; ii++) acc[jj][ii] = fmaf(bv[jj], av[ii], acc[jj][ii]);
        }
        __syncthreads();
    }
#pragma unroll
    for (int jj = 0; jj < 8; jj++) {
        int j = j0 + ty * 8 + jj;
        float b = bias[j];
        float* op = out + (size_t)(n * CC + j) * LL + l0 + tx * 8;
        *(float4*)op = make_float4(acc[jj][0] + b, acc[jj][1] + b,
                                   acc[jj][2] + b, acc[jj][3] + b);
        *(float4*)(op + 4) = make_float4(acc[jj][4] + b, acc[jj][5] + b,
                                         acc[jj][6] + b, acc[jj][7] + b);
    }
}

// ---------------------------------------------------------------------------
extern "C" void kernel_launch(void* const* d_in, const int* in_sizes, int n_in,
                              void* d_out, int out_size) {
    const float* x      = (const float*)d_in[0];
    const float* w_qkv  = (const float*)d_in[1];
    const float* b_qkv  = (const float*)d_in[2];
    const float* w_proj = (const float*)d_in[3];
    const float* b_proj = (const float*)d_in[4];
    const float* w_dc   = (const float*)d_in[5];
    float* out = (float*)d_out;
    (void)in_sizes; (void)n_in; (void)out_size;

    k_gemm_qkv<<<dim3(J3 / 128, (NB * LL) / 128), 256>>>(x, w_qkv, b_qkv);
    k_zero_attn<<<(NH * DD * DD + 255) / 256, 256>>>();
    k_attn<<<dim3(NH, SPLIT), 256>>>();
    k_out<<<NH * (LL / TOK), 128>>>(w_dc);
    k_proj<<<dim3(CC / 128, (NB * LL) / 128), 256>>>(w_proj, b_proj, out);
}

// round 6
// speedup vs baseline: 1.2635x; 1.0244x over previous
#include <cuda_runtime.h>
#include <cuda_bf16.h>
#include <cstdint>

// LinAngularAttention — round 5: mma.sync bf16-split GEMMs (tcgen05 is rejected
// by the harness's sm_103 (non-'a') ptxas target; mma.sync is baseline PTX).

#define NB 8
#define CC 256
#define HH 8
#define DD 32
#define LL 4096
#define J3 768
#define NH (NB*HH)
#define SPLIT 16
#define TOK 128

__device__ float g_qkv[(size_t)NB * LL * J3];            // [N,L,3C] fp32; q,k normalized
__device__ float g_attn[NH * DD * DD];
__device__ __nv_bfloat16 g_xs[(size_t)NB * LL * 512];    // [N,L, hi256|lo256]
__device__ __nv_bfloat16 g_mids[(size_t)NB * LL * 512];  // [N,L, hi256|lo256]
__device__ __nv_bfloat16 g_wq[J3 * 512];                 // [768, hi256|lo256]
__device__ __nv_bfloat16 g_wp[CC * 512];                 // [256, hi256|lo256]

__device__ __forceinline__ uint32_t smem_to_u32(const void* p) {
    uint32_t a;
    asm("{ .reg .u64 t; cvta.to.shared.u64 t, %1; cvt.u32.u64 %0, t; }" : "=r"(a) : "l"(p));
    return a;
}
__device__ __forceinline__ void ldsm4(uint32_t* d, uint32_t addr) {
    asm volatile("ldmatrix.sync.aligned.m8n8.x4.shared.b16 {%0,%1,%2,%3}, [%4];"
                 : "=r"(d[0]), "=r"(d[1]), "=r"(d[2]), "=r"(d[3]) : "r"(addr));
}
__device__ __forceinline__ void mma16816(float* c, const uint32_t* a, const uint32_t* b) {
    asm volatile("mma.sync.aligned.m16n8k16.row.col.f32.bf16.bf16.f32 "
                 "{%0,%1,%2,%3}, {%4,%5,%6,%7}, {%8,%9}, {%0,%1,%2,%3};"
                 : "+f"(c[0]), "+f"(c[1]), "+f"(c[2]), "+f"(c[3])
                 : "r"(a[0]), "r"(a[1]), "r"(a[2]), "r"(a[3]), "r"(b[0]), "r"(b[1]));
}
// 16B-chunk swizzle for 64B rows: conflict-free LDSM + STS.128
#define SWZ(r, c) ((r) * 4 + ((c) ^ (((r) >> 1) & 3)))

// ===================== split kernels =====================
__global__ void k_split_x(const float* __restrict__ x) {
    __shared__ float tile[32][33];
    const int l0 = blockIdx.x * 32, c0 = blockIdx.y * 32, n = blockIdx.z;
    const int tx = threadIdx.x, ty = threadIdx.y;
#pragma unroll
    for (int k = 0; k < 4; k++)
        tile[ty + 8 * k][tx] = x[((size_t)n * CC + c0 + ty + 8 * k) * LL + l0 + tx];
    __syncthreads();
#pragma unroll
    for (int k = 0; k < 4; k++) {
        int l = l0 + ty + 8 * k;
        float f = tile[tx][ty + 8 * k];
        __nv_bfloat16 hi = __float2bfloat16(f);
        __nv_bfloat16 lo = __float2bfloat16(f - __bfloat162float(hi));
        size_t rb = ((size_t)(n * LL + l)) * 512 + c0 + tx;
        g_xs[rb] = hi; g_xs[rb + 256] = lo;
    }
}
__global__ void k_split_wq(const float* __restrict__ w) {
    int idx = blockIdx.x * 256 + threadIdx.x;
    if (idx >= J3 * 256) return;
    int j = idx >> 8, c = idx & 255;
    float f = w[idx];
    __nv_bfloat16 hi = __float2bfloat16(f);
    __nv_bfloat16 lo = __float2bfloat16(f - __bfloat162float(hi));
    g_wq[(size_t)j * 512 + c] = hi;
    g_wq[(size_t)j * 512 + 256 + c] = lo;
}
__global__ void k_split_wp(const float* __restrict__ w) {
    int idx = blockIdx.x * 256 + threadIdx.x;
    if (idx >= CC * 256) return;
    int j = idx >> 8, c = idx & 255;
    float f = w[idx];
    __nv_bfloat16 hi = __float2bfloat16(f);
    __nv_bfloat16 lo = __float2bfloat16(f - __bfloat162float(hi));
    g_wp[(size_t)j * 512 + c] = hi;
    g_wp[(size_t)j * 512 + 256 + c] = lo;
}

// ===================== mma.sync GEMM =====================
// C[m, j] = sum over 3 split segments of A[m,:]·B[j,:]; BM=128, BN=64, BK=32.
// 4 warps: wm in {0,1} (64 rows), wn in {0,1} (32 cols). Warp tile 64x32.
template<bool IS_QKV>
__global__ __launch_bounds__(128) void k_mma(const float* __restrict__ bias,
                                             float* __restrict__ outp) {
    __shared__ __align__(16) __nv_bfloat16 As[128 * 32];
    __shared__ __align__(16) __nv_bfloat16 Bs[64 * 32];
    __shared__ float Cs[32][136];
    const int tid = threadIdx.x;
    const int warp = tid >> 5, lane = tid & 31;
    const int wm = warp & 1, wn = warp >> 1;
    const int j0 = blockIdx.x * 64;
    const int m0 = blockIdx.y * 128;
    const int n = m0 >> 12, l0 = m0 & 4095;

    const __nv_bfloat16* Ab = (IS_QKV ? g_xs : g_mids) + (size_t)(n * LL + l0) * 512;
    const __nv_bfloat16* Bb = (IS_QKV ? g_wq : g_wp) + (size_t)j0 * 512;
    const uint32_t as_base = smem_to_u32(As);
    const uint32_t bs_base = smem_to_u32(Bs);

    const int rA = tid;               // 0..127: own row, 4 chunks
    const int rB = tid & 63;          // 0..63:  own row, 2 chunks
    const int cB = (tid >> 6) * 2;

    float acc[4][4][4] = {};
    uint4 ra[4], rb[2];
#pragma unroll
    for (int c = 0; c < 4; c++) ra[c] = *(const uint4*)(Ab + (size_t)rA * 512 + c * 8);
#pragma unroll
    for (int i = 0; i < 2; i++) rb[i] = *(const uint4*)(Bb + (size_t)rB * 512 + (cB + i) * 8);

    for (int it = 0; it < 24; it++) {
#pragma unroll
        for (int c = 0; c < 4; c++) *(uint4*)(As + 8 * SWZ(rA, c)) = ra[c];
#pragma unroll
        for (int i = 0; i < 2; i++) *(uint4*)(Bs + 8 * SWZ(rB, cB + i)) = rb[i];
        __syncthreads();
        if (it < 23) {
            int it2 = it + 1, seg = it2 >> 3, kc = it2 & 7;
            int colA = ((seg == 2) ? 256 : 0) + kc * 32;
            int colB = ((seg == 1) ? 256 : 0) + kc * 32;
#pragma unroll
            for (int c = 0; c < 4; c++)
                ra[c] = *(const uint4*)(Ab + (size_t)rA * 512 + colA + c * 8);
#pragma unroll
            for (int i = 0; i < 2; i++)
                rb[i] = *(const uint4*)(Bb + (size_t)rB * 512 + colB + (cB + i) * 8);
        }
#pragma unroll
        for (int kk = 0; kk < 2; kk++) {
            uint32_t a[4][4], b[4][2];
#pragma unroll
            for (int mb = 0; mb < 4; mb++) {
                int r = wm * 64 + mb * 16 + (lane & 15);
                int c = kk * 2 + (lane >> 4);
                ldsm4(a[mb], as_base + 16 * SWZ(r, c));
            }
#pragma unroll
            for (int np = 0; np < 2; np++) {
                int r = wn * 32 + np * 16 + ((lane >> 4) & 1) * 8 + (lane & 7);
                int c = kk * 2 + ((lane >> 3) & 1);
                uint32_t t4[4];
                ldsm4(t4, bs_base + 16 * SWZ(r, c));
                b[np * 2][0] = t4[0]; b[np * 2][1] = t4[1];
                b[np * 2 + 1][0] = t4[2]; b[np * 2 + 1][1] = t4[3];
            }
#pragma unroll
            for (int mb = 0; mb < 4; mb++)
#pragma unroll
                for (int nb = 0; nb < 4; nb++)
                    mma16816(acc[mb][nb], a[mb], b[nb]);
        }
        __syncthreads();
    }

    if (IS_QKV) {
        // bias + per-head l2-norm (head = warp's 32 cols) -> g_qkv fp32
        const bool donorm = (j0 < 512);
#pragma unroll
        for (int mb = 0; mb < 4; mb++) {
            float vlo[4][2], vhi[4][2];
            float s_lo = 0.f, s_hi = 0.f;
#pragma unroll
            for (int nb = 0; nb < 4; nb++) {
                int j = j0 + wn * 32 + nb * 8 + (lane & 3) * 2;
                float b0 = __ldg(bias + j), b1 = __ldg(bias + j + 1);
                vlo[nb][0] = acc[mb][nb][0] + b0; vlo[nb][1] = acc[mb][nb][1] + b1;
                vhi[nb][0] = acc[mb][nb][2] + b0; vhi[nb][1] = acc[mb][nb][3] + b1;
                s_lo += vlo[nb][0] * vlo[nb][0] + vlo[nb][1] * vlo[nb][1];
                s_hi += vhi[nb][0] * vhi[nb][0] + vhi[nb][1] * vhi[nb][1];
            }
            s_lo += __shfl_xor_sync(0xffffffffu, s_lo, 1);
            s_lo += __shfl_xor_sync(0xffffffffu, s_lo, 2);
            s_hi += __shfl_xor_sync(0xffffffffu, s_hi, 1);
            s_hi += __shfl_xor_sync(0xffffffffu, s_hi, 2);
            float rlo = donorm ? rsqrtf(s_lo) : 1.f;
            float rhi = donorm ? rsqrtf(s_hi) : 1.f;
            int m = m0 + wm * 64 + mb * 16 + (lane >> 2);
#pragma unroll
            for (int nb = 0; nb < 4; nb++) {
                int j = j0 + wn * 32 + nb * 8 + (lane & 3) * 2;
                float2 o0 = make_float2(vlo[nb][0] * rlo, vlo[nb][1] * rlo);
                float2 o1 = make_float2(vhi[nb][0] * rhi, vhi[nb][1] * rhi);
                *(float2*)(g_qkv + (size_t)m * J3 + j) = o0;
                *(float2*)(g_qkv + (size_t)(m + 8) * J3 + j) = o1;
            }
        }
    } else {
        // transpose through smem for coalesced NCHW stores
        for (int slice = 0; slice < 2; slice++) {
            if (wn == slice) {
#pragma unroll
                for (int mb = 0; mb < 4; mb++)
#pragma unroll
                    for (int nb = 0; nb < 4; nb++) {
                        int jl = nb * 8 + (lane & 3) * 2;
                        int r = wm * 64 + mb * 16 + (lane >> 2);
                        Cs[jl][r]         = acc[mb][nb][0];
                        Cs[jl + 1][r]     = acc[mb][nb][1];
                        Cs[jl][r + 8]     = acc[mb][nb][2];
                        Cs[jl + 1][r + 8] = acc[mb][nb][3];
                    }
            }
            __syncthreads();
#pragma unroll
            for (int rr = 0; rr < 8; rr++) {
                int idx = rr * 128 + tid;
                int j = idx >> 5, f4 = idx & 31;
                float b = __ldg(bias + j0 + slice * 32 + j);
                float4 v = *(float4*)&Cs[j][f4 * 4];
                v.x += b; v.y += b; v.z += b; v.w += b;
                *(float4*)(outp + (size_t)(n * CC + j0 + slice * 32 + j) * LL + l0 + f4 * 4) = v;
            }
            __syncthreads();
        }
    }
}

// ===================== attn =====================
__global__ void k_zero_attn() {
    int i = blockIdx.x * 256 + threadIdx.x;
    if (i < NH * DD * DD) g_attn[i] = 0.f;
}
__global__ __launch_bounds__(256) void k_attn() {
    __shared__ float ks[32][32];
    __shared__ float vs[32][32];
    const int nh = blockIdx.x, chunk = blockIdx.y;
    const int n = nh >> 3, hh = nh & 7;
    const int tid = threadIdx.x;
    const int d = tid >> 3, e4 = tid & 7;
    const int lbase = chunk * (LL / SPLIT);
    const float* base = g_qkv + (size_t)n * LL * J3 + hh * DD;
    const int r = tid >> 3, c4 = (tid & 7) * 4;
    float acc[4] = {};
    for (int t0 = 0; t0 < LL / SPLIT; t0 += 32) {
        const float* rp = base + (size_t)(lbase + t0 + r) * J3;
        *(float4*)&ks[r][c4] = *(const float4*)(rp + CC + c4);
        *(float4*)&vs[r][c4] = *(const float4*)(rp + 2 * CC + c4);
        __syncthreads();
#pragma unroll
        for (int rr = 0; rr < 32; rr++) {
            float kk = ks[rr][d];
            float4 vv = *(const float4*)&vs[rr][e4 * 4];
            acc[0] = fmaf(kk, vv.x, acc[0]); acc[1] = fmaf(kk, vv.y, acc[1]);
            acc[2] = fmaf(kk, vv.z, acc[2]); acc[3] = fmaf(kk, vv.w, acc[3]);
        }
        __syncthreads();
    }
    float* ap = g_attn + nh * (DD * DD) + d * DD + e4 * 4;
    atomicAdd(ap + 0, acc[0]); atomicAdd(ap + 1, acc[1]);
    atomicAdd(ap + 2, acc[2]); atomicAdd(ap + 3, acc[3]);
}

// ===================== fused epilogue -> split mid =====================
__device__ __forceinline__ uint32_t pk2(float a, float b) {
    __nv_bfloat162 t = __floats2bfloat162_rn(a, b);
    return *reinterpret_cast<uint32_t*>(&t);
}
__global__ __launch_bounds__(256) void k_out(const float* __restrict__ wdc) {
    __shared__ float att[32][32];
    __shared__ float q_s[TOK][33];
    __shared__ float v_s[TOK + 8][32];
    __shared__ float ws9[9];
    const int bid = blockIdx.x;
    const int nh = bid >> 5, ltile = bid & 31;
    const int n = nh >> 3, hh = nh & 7;
    const int tid = threadIdx.x;
    const int l0 = ltile * TOK;

    const float INV_PI = 0.3183098861837907f;
    for (int i = tid; i < 1024; i += 256) ((float*)att)[i] = g_attn[nh * 1024 + i] * INV_PI;
    if (tid < 9) ws9[tid] = wdc[hh * 9 + tid];

    const float* qb = g_qkv + (size_t)n * LL * J3 + hh * DD;
    for (int i = tid; i < TOK * 8; i += 256) {
        int r = i >> 3, c4 = (i & 7) * 4;
        float4 v4 = *(const float4*)(qb + (size_t)(l0 + r) * J3 + c4);
        q_s[r][c4 + 0] = v4.x; q_s[r][c4 + 1] = v4.y;
        q_s[r][c4 + 2] = v4.z; q_s[r][c4 + 3] = v4.w;
    }
    for (int i = tid; i < (TOK + 8) * 8; i += 256) {
        int r = i >> 3, c4 = i & 7;
        int l = l0 - 4 + r;
        float4 v4 = make_float4(0.f, 0.f, 0.f, 0.f);
        if ((unsigned)l < (unsigned)LL)
            v4 = *(const float4*)(qb + (size_t)l * J3 + 2 * CC + c4 * 4);
        *(float4*)&v_s[r][(c4 ^ (r & 7)) * 4] = v4;
    }
    __syncthreads();

    const int t = tid >> 1, h = tid & 1;
    const int l = l0 + t;

    float4 o[4];
    {
        int r = t + 4;
#pragma unroll
        for (int j = 0; j < 4; j++) {
            float4 vv = *(const float4*)&v_s[r][((h * 4 + j) ^ (r & 7)) * 4];
            o[j] = make_float4(0.5f * vv.x, 0.5f * vv.y, 0.5f * vv.z, 0.5f * vv.w);
        }
    }
#pragma unroll 4
    for (int d = 0; d < 32; d++) {
        float qd = q_s[t][d];
#pragma unroll
        for (int j = 0; j < 4; j++) {
            float4 a = *(const float4*)&att[d][h * 16 + j * 4];
            o[j].x = fmaf(qd, a.x, o[j].x); o[j].y = fmaf(qd, a.y, o[j].y);
            o[j].z = fmaf(qd, a.z, o[j].z); o[j].w = fmaf(qd, a.w, o[j].w);
        }
    }
    float s = 0.f;
#pragma unroll
    for (int j = 0; j < 4; j++)
        s += o[j].x * o[j].x + o[j].y * o[j].y + o[j].z * o[j].z + o[j].w * o[j].w;
    s += __shfl_xor_sync(0xffffffffu, s, 1);
    float rn = rsqrtf(s);
#pragma unroll
    for (int j = 0; j < 4; j++) { o[j].x *= rn; o[j].y *= rn; o[j].z *= rn; o[j].w *= rn; }
#pragma unroll
    for (int tap = 0; tap < 9; tap++) {
        float wt = ws9[tap];
        int r = t + tap;
#pragma unroll
        for (int j = 0; j < 4; j++) {
            float4 vv = *(const float4*)&v_s[r][((h * 4 + j) ^ (r & 7)) * 4];
            o[j].x = fmaf(wt, vv.x, o[j].x); o[j].y = fmaf(wt, vv.y, o[j].y);
            o[j].z = fmaf(wt, vv.z, o[j].z); o[j].w = fmaf(wt, vv.w, o[j].w);
        }
    }
    float f[16] = {o[0].x, o[0].y, o[0].z, o[0].w, o[1].x, o[1].y, o[1].z, o[1].w,
                   o[2].x, o[2].y, o[2].z, o[2].w, o[3].x, o[3].y, o[3].z, o[3].w};
    float fh[16], fl[16];
#pragma unroll
    for (int i = 0; i < 16; i++) {
        __nv_bfloat16 hb = __float2bfloat16(f[i]);
        fh[i] = __bfloat162float(hb);
        fl[i] = f[i] - fh[i];
    }
    const int cb = hh * 32 + h * 16;
    __nv_bfloat16* row = g_mids + (size_t)(n * LL + l) * 512;
    uint4 hi0 = make_uint4(pk2(fh[0], fh[1]), pk2(fh[2], fh[3]), pk2(fh[4], fh[5]), pk2(fh[6], fh[7]));
    uint4 hi1 = make_uint4(pk2(fh[8], fh[9]), pk2(fh[10], fh[11]), pk2(fh[12], fh[13]), pk2(fh[14], fh[15]));
    uint4 lo0 = make_uint4(pk2(fl[0], fl[1]), pk2(fl[2], fl[3]), pk2(fl[4], fl[5]), pk2(fl[6], fl[7]));
    uint4 lo1 = make_uint4(pk2(fl[8], fl[9]), pk2(fl[10], fl[11]), pk2(fl[12], fl[13]), pk2(fl[14], fl[15]));
    *(uint4*)(row + cb) = hi0;
    *(uint4*)(row + cb + 8) = hi1;
    *(uint4*)(row + 256 + cb) = lo0;
    *(uint4*)(row + 256 + cb + 8) = lo1;
}

// ===================== launch =====================
extern "C" void kernel_launch(void* const* d_in, const int* in_sizes, int n_in,
                              void* d_out, int out_size) {
    const float* x      = (const float*)d_in[0];
    const float* w_qkv  = (const float*)d_in[1];
    const float* b_qkv  = (const float*)d_in[2];
    const float* w_proj = (const float*)d_in[3];
    const float* b_proj = (const float*)d_in[4];
    const float* w_dc   = (const float*)d_in[5];
    float* out = (float*)d_out;
    (void)in_sizes; (void)n_in; (void)out_size;

    k_split_x<<<dim3(LL / 32, CC / 32, NB), dim3(32, 8)>>>(x);
    k_split_wq<<<(J3 * 256) / 256, 256>>>(w_qkv);
    k_split_wp<<<(CC * 256) / 256, 256>>>(w_proj);

    k_mma<true><<<dim3(J3 / 64, (NB * LL) / 128), 128>>>(b_qkv, nullptr);

    k_zero_attn<<<(NH * DD * DD + 255) / 256, 256>>>();
    k_attn<<<dim3(NH, SPLIT), 256>>>();
    k_out<<<NH * (LL / TOK), 256>>>(w_dc);

    k_mma<false><<<dim3(CC / 64, (NB * LL) / 128), 128>>>(b_proj, out);
}

// round 7
// speedup vs baseline: 1.9596x; 1.5510x over previous
#include <cuda_runtime.h>
#include <cuda_bf16.h>
#include <cstdint>

// LinAngularAttention — round 6: cp.async double-buffered mma.sync GEMMs

#define NB 8
#define CC 256
#define HH 8
#define DD 32
#define LL 4096
#define J3 768
#define NH (NB*HH)
#define SPLIT 16
#define TOK 128

__device__ float g_qkv[(size_t)NB * LL * J3];            // [N,L,3C] fp32; q,k normalized
__device__ float g_attn[NH * DD * DD];
__device__ __nv_bfloat16 g_xs[(size_t)NB * LL * 512];    // [N,L, hi256|lo256]
__device__ __nv_bfloat16 g_mids[(size_t)NB * LL * 512];  // [N,L, hi256|lo256]
__device__ __nv_bfloat16 g_wq[J3 * 512];                 // [768, hi256|lo256]
__device__ __nv_bfloat16 g_wp[CC * 512];                 // [256, hi256|lo256]

__device__ __forceinline__ uint32_t smem_to_u32(const void* p) {
    uint32_t a;
    asm("{ .reg .u64 t; cvta.to.shared.u64 t, %1; cvt.u32.u64 %0, t; }" : "=r"(a) : "l"(p));
    return a;
}
__device__ __forceinline__ void ldsm4(uint32_t* d, uint32_t addr) {
    asm volatile("ldmatrix.sync.aligned.m8n8.x4.shared.b16 {%0,%1,%2,%3}, [%4];"
                 : "=r"(d[0]), "=r"(d[1]), "=r"(d[2]), "=r"(d[3]) : "r"(addr));
}
__device__ __forceinline__ void mma16816(float* c, const uint32_t* a, const uint32_t* b) {
    asm volatile("mma.sync.aligned.m16n8k16.row.col.f32.bf16.bf16.f32 "
                 "{%0,%1,%2,%3}, {%4,%5,%6,%7}, {%8,%9}, {%0,%1,%2,%3};"
                 : "+f"(c[0]), "+f"(c[1]), "+f"(c[2]), "+f"(c[3])
                 : "r"(a[0]), "r"(a[1]), "r"(a[2]), "r"(a[3]), "r"(b[0]), "r"(b[1]));
}
__device__ __forceinline__ void cpasync16(uint32_t dst, const void* src) {
    asm volatile("cp.async.cg.shared.global [%0], [%1], 16;" :: "r"(dst), "l"(src) : "memory");
}
#define CP_COMMIT() asm volatile("cp.async.commit_group;" ::: "memory")
#define CP_WAIT1()  asm volatile("cp.async.wait_group 1;" ::: "memory")
#define CP_WAIT0()  asm volatile("cp.async.wait_group 0;" ::: "memory")
// 16B-chunk swizzle for 64B rows: conflict-free LDSM + cp.async stores
#define SWZ(r, c) ((r) * 4 + ((c) ^ (((r) >> 1) & 3)))

// ===================== split kernels =====================
__global__ void k_split_x(const float* __restrict__ x) {
    __shared__ float tile[32][33];
    const int l0 = blockIdx.x * 32, c0 = blockIdx.y * 32, n = blockIdx.z;
    const int tx = threadIdx.x, ty = threadIdx.y;
#pragma unroll
    for (int k = 0; k < 4; k++)
        tile[ty + 8 * k][tx] = x[((size_t)n * CC + c0 + ty + 8 * k) * LL + l0 + tx];
    __syncthreads();
#pragma unroll
    for (int k = 0; k < 4; k++) {
        int l = l0 + ty + 8 * k;
        float f = tile[tx][ty + 8 * k];
        __nv_bfloat16 hi = __float2bfloat16(f);
        __nv_bfloat16 lo = __float2bfloat16(f - __bfloat162float(hi));
        size_t rb = ((size_t)(n * LL + l)) * 512 + c0 + tx;
        g_xs[rb] = hi; g_xs[rb + 256] = lo;
    }
}
__global__ void k_split_wq(const float* __restrict__ w) {
    int idx = blockIdx.x * 256 + threadIdx.x;
    if (idx >= J3 * 256) return;
    int j = idx >> 8, c = idx & 255;
    float f = w[idx];
    __nv_bfloat16 hi = __float2bfloat16(f);
    __nv_bfloat16 lo = __float2bfloat16(f - __bfloat162float(hi));
    g_wq[(size_t)j * 512 + c] = hi;
    g_wq[(size_t)j * 512 + 256 + c] = lo;
}
__global__ void k_split_wp(const float* __restrict__ w) {
    int idx = blockIdx.x * 256 + threadIdx.x;
    if (idx >= CC * 256) return;
    int j = idx >> 8, c = idx & 255;
    float f = w[idx];
    __nv_bfloat16 hi = __float2bfloat16(f);
    __nv_bfloat16 lo = __float2bfloat16(f - __bfloat162float(hi));
    g_wp[(size_t)j * 512 + c] = hi;
    g_wp[(size_t)j * 512 + 256 + c] = lo;
}

// ===================== mma.sync GEMM =====================
// C[m,j] = sum over 3 split segments; BM=128, BN=128, BK=32, 8 warps (2x4),
// warp tile 64x32, cp.async double buffering.
template<bool IS_QKV>
__global__ __launch_bounds__(256) void k_mma(const float* __restrict__ bias,
                                             float* __restrict__ outp) {
    __shared__ __align__(16) __nv_bfloat16 As[2][128 * 32];
    __shared__ __align__(16) __nv_bfloat16 Bs[2][128 * 32];
    const int tid = threadIdx.x;
    const int warp = tid >> 5, lane = tid & 31;
    const int wm = warp >> 2, wn = warp & 3;      // 2 x 4
    const int j0 = blockIdx.x * 128;
    const int m0 = blockIdx.y * 128;
    const int n = m0 >> 12, l0 = m0 & 4095;

    const __nv_bfloat16* Ab = (IS_QKV ? g_xs : g_mids) + (size_t)(n * LL + l0) * 512;
    const __nv_bfloat16* Bb = (IS_QKV ? g_wq : g_wp) + (size_t)j0 * 512;
    const uint32_t as_base = smem_to_u32(As);
    const uint32_t bs_base = smem_to_u32(Bs);

    const int rL = tid >> 1, cL = (tid & 1) * 2;  // loader: row, 2 chunks of 16B

    auto issue = [&](int it, int s) {
        int seg = it >> 3, kc = it & 7;
        int colA = ((seg == 2) ? 256 : 0) + kc * 32;
        int colB = ((seg == 1) ? 256 : 0) + kc * 32;
#pragma unroll
        for (int i = 0; i < 2; i++) {
            cpasync16(as_base + (s * 4096 + 8 * SWZ(rL, cL + i)) * 2,
                      Ab + (size_t)rL * 512 + colA + (cL + i) * 8);
            cpasync16(bs_base + (s * 4096 + 8 * SWZ(rL, cL + i)) * 2,
                      Bb + (size_t)rL * 512 + colB + (cL + i) * 8);
        }
        CP_COMMIT();
    };

    float acc[4][4][4] = {};
    issue(0, 0);
    for (int it = 0; it < 24; it++) {
        int s = it & 1;
        if (it < 23) { issue(it + 1, s ^ 1); CP_WAIT1(); }
        else CP_WAIT0();
        __syncthreads();
        const uint32_t ab = as_base + s * 8192;
        const uint32_t bb = bs_base + s * 8192;
#pragma unroll
        for (int kk = 0; kk < 2; kk++) {
            uint32_t a[4][4], b[4][2];
#pragma unroll
            for (int mb = 0; mb < 4; mb++) {
                int r = wm * 64 + mb * 16 + (lane & 15);
                int c = kk * 2 + (lane >> 4);
                ldsm4(a[mb], ab + 16 * SWZ(r, c));
            }
#pragma unroll
            for (int np = 0; np < 2; np++) {
                int r = wn * 32 + np * 16 + ((lane >> 4) & 1) * 8 + (lane & 7);
                int c = kk * 2 + ((lane >> 3) & 1);
                uint32_t t4[4];
                ldsm4(t4, bb + 16 * SWZ(r, c));
                b[np * 2][0] = t4[0]; b[np * 2][1] = t4[1];
                b[np * 2 + 1][0] = t4[2]; b[np * 2 + 1][1] = t4[3];
            }
#pragma unroll
            for (int mb = 0; mb < 4; mb++)
#pragma unroll
                for (int nb = 0; nb < 4; nb++)
                    mma16816(acc[mb][nb], a[mb], b[nb]);
        }
        __syncthreads();
    }

    if constexpr (IS_QKV) {
        // bias + per-head l2-norm (head = warp's 32 cols) -> g_qkv fp32
        const bool donorm = (j0 + wn * 32 < 512);
#pragma unroll
        for (int mb = 0; mb < 4; mb++) {
            float vlo[4][2], vhi[4][2];
            float s_lo = 0.f, s_hi = 0.f;
#pragma unroll
            for (int nb = 0; nb < 4; nb++) {
                int j = j0 + wn * 32 + nb * 8 + (lane & 3) * 2;
                float b0 = __ldg(bias + j), b1 = __ldg(bias + j + 1);
                vlo[nb][0] = acc[mb][nb][0] + b0; vlo[nb][1] = acc[mb][nb][1] + b1;
                vhi[nb][0] = acc[mb][nb][2] + b0; vhi[nb][1] = acc[mb][nb][3] + b1;
                s_lo += vlo[nb][0] * vlo[nb][0] + vlo[nb][1] * vlo[nb][1];
                s_hi += vhi[nb][0] * vhi[nb][0] + vhi[nb][1] * vhi[nb][1];
            }
            s_lo += __shfl_xor_sync(0xffffffffu, s_lo, 1);
            s_lo += __shfl_xor_sync(0xffffffffu, s_lo, 2);
            s_hi += __shfl_xor_sync(0xffffffffu, s_hi, 1);
            s_hi += __shfl_xor_sync(0xffffffffu, s_hi, 2);
            float rlo = donorm ? rsqrtf(s_lo) : 1.f;
            float rhi = donorm ? rsqrtf(s_hi) : 1.f;
            int m = m0 + wm * 64 + mb * 16 + (lane >> 2);
#pragma unroll
            for (int nb = 0; nb < 4; nb++) {
                int j = j0 + wn * 32 + nb * 8 + (lane & 3) * 2;
                float2 o0 = make_float2(vlo[nb][0] * rlo, vlo[nb][1] * rlo);
                float2 o1 = make_float2(vhi[nb][0] * rhi, vhi[nb][1] * rhi);
                *(float2*)(g_qkv + (size_t)m * J3 + j) = o0;
                *(float2*)(g_qkv + (size_t)(m + 8) * J3 + j) = o1;
            }
        }
    } else {
        // transpose through smem (aliasing A/B stages) for coalesced NCHW stores
        float (*Cs)[136] = reinterpret_cast<float (*)[136]>(&As[0][0]);
        for (int slice = 0; slice < 4; slice++) {
            if (wn == slice) {
#pragma unroll
                for (int mb = 0; mb < 4; mb++)
#pragma unroll
                    for (int nb = 0; nb < 4; nb++) {
                        int jl = nb * 8 + (lane & 3) * 2;
                        int r = wm * 64 + mb * 16 + (lane >> 2);
                        Cs[jl][r]         = acc[mb][nb][0];
                        Cs[jl + 1][r]     = acc[mb][nb][1];
                        Cs[jl][r + 8]     = acc[mb][nb][2];
                        Cs[jl + 1][r + 8] = acc[mb][nb][3];
                    }
            }
            __syncthreads();
#pragma unroll
            for (int rr = 0; rr < 4; rr++) {
                int idx = rr * 256 + tid;
                int j = idx >> 5, f4 = idx & 31;
                float b = __ldg(bias + j0 + slice * 32 + j);
                float4 v = *(float4*)&Cs[j][f4 * 4];
                v.x += b; v.y += b; v.z += b; v.w += b;
                *(float4*)(outp + (size_t)(n * CC + j0 + slice * 32 + j) * LL + l0 + f4 * 4) = v;
            }
            __syncthreads();
        }
    }
}

// ===================== attn =====================
__global__ void k_zero_attn() {
    int i = blockIdx.x * 256 + threadIdx.x;
    if (i < NH * DD * DD) g_attn[i] = 0.f;
}
__global__ __launch_bounds__(256) void k_attn() {
    __shared__ float ks[32][32];
    __shared__ float vs[32][32];
    const int nh = blockIdx.x, chunk = blockIdx.y;
    const int n = nh >> 3, hh = nh & 7;
    const int tid = threadIdx.x;
    const int d = tid >> 3, e4 = tid & 7;
    const int lbase = chunk * (LL / SPLIT);
    const float* base = g_qkv + (size_t)n * LL * J3 + hh * DD;
    const int r = tid >> 3, c4 = (tid & 7) * 4;
    float acc[4] = {};
    for (int t0 = 0; t0 < LL / SPLIT; t0 += 32) {
        const float* rp = base + (size_t)(lbase + t0 + r) * J3;
        *(float4*)&ks[r][c4] = *(const float4*)(rp + CC + c4);
        *(float4*)&vs[r][c4] = *(const float4*)(rp + 2 * CC + c4);
        __syncthreads();
#pragma unroll
        for (int rr = 0; rr < 32; rr++) {
            float kk = ks[rr][d];
            float4 vv = *(const float4*)&vs[rr][e4 * 4];
            acc[0] = fmaf(kk, vv.x, acc[0]); acc[1] = fmaf(kk, vv.y, acc[1]);
            acc[2] = fmaf(kk, vv.z, acc[2]); acc[3] = fmaf(kk, vv.w, acc[3]);
        }
        __syncthreads();
    }
    float* ap = g_attn + nh * (DD * DD) + d * DD + e4 * 4;
    atomicAdd(ap + 0, acc[0]); atomicAdd(ap + 1, acc[1]);
    atomicAdd(ap + 2, acc[2]); atomicAdd(ap + 3, acc[3]);
}

// ===================== fused epilogue -> split mid =====================
__device__ __forceinline__ uint32_t pk2(float a, float b) {
    __nv_bfloat162 t = __floats2bfloat162_rn(a, b);
    return *reinterpret_cast<uint32_t*>(&t);
}
__global__ __launch_bounds__(256) void k_out(const float* __restrict__ wdc) {
    __shared__ float att[32][32];
    __shared__ float q_s[TOK][33];
    __shared__ float v_s[TOK + 8][32];
    __shared__ float ws9[9];
    const int bid = blockIdx.x;
    const int nh = bid >> 5, ltile = bid & 31;
    const int n = nh >> 3, hh = nh & 7;
    const int tid = threadIdx.x;
    const int l0 = ltile * TOK;

    const float INV_PI = 0.3183098861837907f;
    for (int i = tid; i < 1024; i += 256) ((float*)att)[i] = g_attn[nh * 1024 + i] * INV_PI;
    if (tid < 9) ws9[tid] = wdc[hh * 9 + tid];

    const float* qb = g_qkv + (size_t)n * LL * J3 + hh * DD;
    for (int i = tid; i < TOK * 8; i += 256) {
        int r = i >> 3, c4 = (i & 7) * 4;
        float4 v4 = *(const float4*)(qb + (size_t)(l0 + r) * J3 + c4);
        q_s[r][c4 + 0] = v4.x; q_s[r][c4 + 1] = v4.y;
        q_s[r][c4 + 2] = v4.z; q_s[r][c4 + 3] = v4.w;
    }
    for (int i = tid; i < (TOK + 8) * 8; i += 256) {
        int r = i >> 3, c4 = i & 7;
        int l = l0 - 4 + r;
        float4 v4 = make_float4(0.f, 0.f, 0.f, 0.f);
        if ((unsigned)l < (unsigned)LL)
            v4 = *(const float4*)(qb + (size_t)l * J3 + 2 * CC + c4 * 4);
        *(float4*)&v_s[r][(c4 ^ (r & 7)) * 4] = v4;
    }
    __syncthreads();

    const int t = tid >> 1, h = tid & 1;
    const int l = l0 + t;

    float4 o[4];
    {
        int r = t + 4;
#pragma unroll
        for (int j = 0; j < 4; j++) {
            float4 vv = *(const float4*)&v_s[r][((h * 4 + j) ^ (r & 7)) * 4];
            o[j] = make_float4(0.5f * vv.x, 0.5f * vv.y, 0.5f * vv.z, 0.5f * vv.w);
        }
    }
#pragma unroll 4
    for (int d = 0; d < 32; d++) {
        float qd = q_s[t][d];
#pragma unroll
        for (int j = 0; j < 4; j++) {
            float4 a = *(const float4*)&att[d][h * 16 + j * 4];
            o[j].x = fmaf(qd, a.x, o[j].x); o[j].y = fmaf(qd, a.y, o[j].y);
            o[j].z = fmaf(qd, a.z, o[j].z); o[j].w = fmaf(qd, a.w, o[j].w);
        }
    }
    float s = 0.f;
#pragma unroll
    for (int j = 0; j < 4; j++)
        s += o[j].x * o[j].x + o[j].y * o[j].y + o[j].z * o[j].z + o[j].w * o[j].w;
    s += __shfl_xor_sync(0xffffffffu, s, 1);
    float rn = rsqrtf(s);
#pragma unroll
    for (int j = 0; j < 4; j++) { o[j].x *= rn; o[j].y *= rn; o[j].z *= rn; o[j].w *= rn; }
#pragma unroll
    for (int tap = 0; tap < 9; tap++) {
        float wt = ws9[tap];
        int r = t + tap;
#pragma unroll
        for (int j = 0; j < 4; j++) {
            float4 vv = *(const float4*)&v_s[r][((h * 4 + j) ^ (r & 7)) * 4];
            o[j].x = fmaf(wt, vv.x, o[j].x); o[j].y = fmaf(wt, vv.y, o[j].y);
            o[j].z = fmaf(wt, vv.z, o[j].z); o[j].w = fmaf(wt, vv.w, o[j].w);
        }
    }
    float f[16] = {o[0].x, o[0].y, o[0].z, o[0].w, o[1].x, o[1].y, o[1].z, o[1].w,
                   o[2].x, o[2].y, o[2].z, o[2].w, o[3].x, o[3].y, o[3].z, o[3].w};
    float fh[16], fl[16];
#pragma unroll
    for (int i = 0; i < 16; i++) {
        __nv_bfloat16 hb = __float2bfloat16(f[i]);
        fh[i] = __bfloat162float(hb);
        fl[i] = f[i] - fh[i];
    }
    const int cb = hh * 32 + h * 16;
    __nv_bfloat16* row = g_mids + (size_t)(n * LL + l) * 512;
    uint4 hi0 = make_uint4(pk2(fh[0], fh[1]), pk2(fh[2], fh[3]), pk2(fh[4], fh[5]), pk2(fh[6], fh[7]));
    uint4 hi1 = make_uint4(pk2(fh[8], fh[9]), pk2(fh[10], fh[11]), pk2(fh[12], fh[13]), pk2(fh[14], fh[15]));
    uint4 lo0 = make_uint4(pk2(fl[0], fl[1]), pk2(fl[2], fl[3]), pk2(fl[4], fl[5]), pk2(fl[6], fl[7]));
    uint4 lo1 = make_uint4(pk2(fl[8], fl[9]), pk2(fl[10], fl[11]), pk2(fl[12], fl[13]), pk2(fl[14], fl[15]));
    *(uint4*)(row + cb) = hi0;
    *(uint4*)(row + cb + 8) = hi1;
    *(uint4*)(row + 256 + cb) = lo0;
    *(uint4*)(row + 256 + cb + 8) = lo1;
}

// ===================== launch =====================
extern "C" void kernel_launch(void* const* d_in, const int* in_sizes, int n_in,
                              void* d_out, int out_size) {
    const float* x      = (const float*)d_in[0];
    const float* w_qkv  = (const float*)d_in[1];
    const float* b_qkv  = (const float*)d_in[2];
    const float* w_proj = (const float*)d_in[3];
    const float* b_proj = (const float*)d_in[4];
    const float* w_dc   = (const float*)d_in[5];
    float* out = (float*)d_out;
    (void)in_sizes; (void)n_in; (void)out_size;

    k_split_x<<<dim3(LL / 32, CC / 32, NB), dim3(32, 8)>>>(x);
    k_split_wq<<<(J3 * 256) / 256, 256>>>(w_qkv);
    k_split_wp<<<(CC * 256) / 256, 256>>>(w_proj);

    k_mma<true><<<dim3(J3 / 128, (NB * LL) / 128), 256>>>(b_qkv, nullptr);

    k_zero_attn<<<(NH * DD * DD + 255) / 256, 256>>>();
    k_attn<<<dim3(NH, SPLIT), 256>>>();
    k_out<<<NH * (LL / TOK), 256>>>(w_dc);

    k_mma<false><<<dim3(CC / 128, (NB * LL) / 128), 256>>>(b_proj, out);
}

// round 8
// speedup vs baseline: 1.9615x; 1.0010x over previous
#include <cuda_runtime.h>
#include <cuda_bf16.h>
#include <cstdint>

// LinAngularAttention — round 6: cp.async double-buffered mma.sync GEMMs

#define NB 8
#define CC 256
#define HH 8
#define DD 32
#define LL 4096
#define J3 768
#define NH (NB*HH)
#define SPLIT 16
#define TOK 128

__device__ float g_qkv[(size_t)NB * LL * J3];            // [N,L,3C] fp32; q,k normalized
__device__ float g_attn[NH * DD * DD];
__device__ __nv_bfloat16 g_xs[(size_t)NB * LL * 512];    // [N,L, hi256|lo256]
__device__ __nv_bfloat16 g_mids[(size_t)NB * LL * 512];  // [N,L, hi256|lo256]
__device__ __nv_bfloat16 g_wq[J3 * 512];                 // [768, hi256|lo256]
__device__ __nv_bfloat16 g_wp[CC * 512];                 // [256, hi256|lo256]

__device__ __forceinline__ uint32_t smem_to_u32(const void* p) {
    uint32_t a;
    asm("{ .reg .u64 t; cvta.to.shared.u64 t, %1; cvt.u32.u64 %0, t; }" : "=r"(a) : "l"(p));
    return a;
}
__device__ __forceinline__ void ldsm4(uint32_t* d, uint32_t addr) {
    asm volatile("ldmatrix.sync.aligned.m8n8.x4.shared.b16 {%0,%1,%2,%3}, [%4];"
                 : "=r"(d[0]), "=r"(d[1]), "=r"(d[2]), "=r"(d[3]) : "r"(addr));
}
__device__ __forceinline__ void mma16816(float* c, const uint32_t* a, const uint32_t* b) {
    asm volatile("mma.sync.aligned.m16n8k16.row.col.f32.bf16.bf16.f32 "
                 "{%0,%1,%2,%3}, {%4,%5,%6,%7}, {%8,%9}, {%0,%1,%2,%3};"
                 : "+f"(c[0]), "+f"(c[1]), "+f"(c[2]), "+f"(c[3])
                 : "r"(a[0]), "r"(a[1]), "r"(a[2]), "r"(a[3]), "r"(b[0]), "r"(b[1]));
}
__device__ __forceinline__ void cpasync16(uint32_t dst, const void* src) {
    asm volatile("cp.async.cg.shared.global [%0], [%1], 16;" :: "r"(dst), "l"(src) : "memory");
}
#define CP_COMMIT() asm volatile("cp.async.commit_group;" ::: "memory")
#define CP_WAIT1()  asm volatile("cp.async.wait_group 1;" ::: "memory")
#define CP_WAIT0()  asm volatile("cp.async.wait_group 0;" ::: "memory")
// 16B-chunk swizzle for 64B rows: conflict-free LDSM + cp.async stores
#define SWZ(r, c) ((r) * 4 + ((c) ^ (((r) >> 1) & 3)))

// ===================== split kernels =====================
__global__ void k_split_x(const float* __restrict__ x) {
    __shared__ float tile[32][33];
    const int l0 = blockIdx.x * 32, c0 = blockIdx.y * 32, n = blockIdx.z;
    const int tx = threadIdx.x, ty = threadIdx.y;
#pragma unroll
    for (int k = 0; k < 4; k++)
        tile[ty + 8 * k][tx] = x[((size_t)n * CC + c0 + ty + 8 * k) * LL + l0 + tx];
    __syncthreads();
#pragma unroll
    for (int k = 0; k < 4; k++) {
        int l = l0 + ty + 8 * k;
        float f = tile[tx][ty + 8 * k];
        __nv_bfloat16 hi = __float2bfloat16(f);
        __nv_bfloat16 lo = __float2bfloat16(f - __bfloat162float(hi));
        size_t rb = ((size_t)(n * LL + l)) * 512 + c0 + tx;
        g_xs[rb] = hi; g_xs[rb + 256] = lo;
    }
}
__global__ void k_split_wq(const float* __restrict__ w) {
    int idx = blockIdx.x * 256 + threadIdx.x;
    if (idx >= J3 * 256) return;
    int j = idx >> 8, c = idx & 255;
    float f = w[idx];
    __nv_bfloat16 hi = __float2bfloat16(f);
    __nv_bfloat16 lo = __float2bfloat16(f - __bfloat162float(hi));
    g_wq[(size_t)j * 512 + c] = hi;
    g_wq[(size_t)j * 512 + 256 + c] = lo;
}
__global__ void k_split_wp(const float* __restrict__ w) {
    int idx = blockIdx.x * 256 + threadIdx.x;
    if (idx >= CC * 256) return;
    int j = idx >> 8, c = idx & 255;
    float f = w[idx];
    __nv_bfloat16 hi = __float2bfloat16(f);
    __nv_bfloat16 lo = __float2bfloat16(f - __bfloat162float(hi));
    g_wp[(size_t)j * 512 + c] = hi;
    g_wp[(size_t)j * 512 + 256 + c] = lo;
}

// ===================== mma.sync GEMM =====================
// C[m,j] = sum over 3 split segments; BM=128, BN=128, BK=32, 8 warps (2x4),
// warp tile 64x32, cp.async double buffering.
template<bool IS_QKV>
__global__ __launch_bounds__(256) void k_mma(const float* __restrict__ bias,
                                             float* __restrict__ outp) {
    __shared__ __align__(16) __nv_bfloat16 As[2][128 * 32];
    __shared__ __align__(16) __nv_bfloat16 Bs[2][128 * 32];
    const int tid = threadIdx.x;
    const int warp = tid >> 5, lane = tid & 31;
    const int wm = warp >> 2, wn = warp & 3;      // 2 x 4
    const int j0 = blockIdx.x * 128;
    const int m0 = blockIdx.y * 128;
    const int n = m0 >> 12, l0 = m0 & 4095;

    const __nv_bfloat16* Ab = (IS_QKV ? g_xs : g_mids) + (size_t)(n * LL + l0) * 512;
    const __nv_bfloat16* Bb = (IS_QKV ? g_wq : g_wp) + (size_t)j0 * 512;
    const uint32_t as_base = smem_to_u32(As);
    const uint32_t bs_base = smem_to_u32(Bs);

    const int rL = tid >> 1, cL = (tid & 1) * 2;  // loader: row, 2 chunks of 16B

    auto issue = [&](int it, int s) {
        int seg = it >> 3, kc = it & 7;
        int colA = ((seg == 2) ? 256 : 0) + kc * 32;
        int colB = ((seg == 1) ? 256 : 0) + kc * 32;
#pragma unroll
        for (int i = 0; i < 2; i++) {
            cpasync16(as_base + (s * 4096 + 8 * SWZ(rL, cL + i)) * 2,
                      Ab + (size_t)rL * 512 + colA + (cL + i) * 8);
            cpasync16(bs_base + (s * 4096 + 8 * SWZ(rL, cL + i)) * 2,
                      Bb + (size_t)rL * 512 + colB + (cL + i) * 8);
        }
        CP_COMMIT();
    };

    float acc[4][4][4] = {};
    issue(0, 0);
    for (int it = 0; it < 24; it++) {
        int s = it & 1;
        if (it < 23) { issue(it + 1, s ^ 1); CP_WAIT1(); }
        else CP_WAIT0();
        __syncthreads();
        const uint32_t ab = as_base + s * 8192;
        const uint32_t bb = bs_base + s * 8192;
#pragma unroll
        for (int kk = 0; kk < 2; kk++) {
            uint32_t a[4][4], b[4][2];
#pragma unroll
            for (int mb = 0; mb < 4; mb++) {
                int r = wm * 64 + mb * 16 + (lane & 15);
                int c = kk * 2 + (lane >> 4);
                ldsm4(a[mb], ab + 16 * SWZ(r, c));
            }
#pragma unroll
            for (int np = 0; np < 2; np++) {
                int r = wn * 32 + np * 16 + ((lane >> 4) & 1) * 8 + (lane & 7);
                int c = kk * 2 + ((lane >> 3) & 1);
                uint32_t t4[4];
                ldsm4(t4, bb + 16 * SWZ(r, c));
                b[np * 2][0] = t4[0]; b[np * 2][1] = t4[1];
                b[np * 2 + 1][0] = t4[2]; b[np * 2 + 1][1] = t4[3];
            }
#pragma unroll
            for (int mb = 0; mb < 4; mb++)
#pragma unroll
                for (int nb = 0; nb < 4; nb++)
                    mma16816(acc[mb][nb], a[mb], b[nb]);
        }
        __syncthreads();
    }

    if constexpr (IS_QKV) {
        // bias + per-head l2-norm (head = warp's 32 cols) -> g_qkv fp32
        const bool donorm = (j0 + wn * 32 < 512);
#pragma unroll
        for (int mb = 0; mb < 4; mb++) {
            float vlo[4][2], vhi[4][2];
            float s_lo = 0.f, s_hi = 0.f;
#pragma unroll
            for (int nb = 0; nb < 4; nb++) {
                int j = j0 + wn * 32 + nb * 8 + (lane & 3) * 2;
                float b0 = __ldg(bias + j), b1 = __ldg(bias + j + 1);
                vlo[nb][0] = acc[mb][nb][0] + b0; vlo[nb][1] = acc[mb][nb][1] + b1;
                vhi[nb][0] = acc[mb][nb][2] + b0; vhi[nb][1] = acc[mb][nb][3] + b1;
                s_lo += vlo[nb][0] * vlo[nb][0] + vlo[nb][1] * vlo[nb][1];
                s_hi += vhi[nb][0] * vhi[nb][0] + vhi[nb][1] * vhi[nb][1];
            }
            s_lo += __shfl_xor_sync(0xffffffffu, s_lo, 1);
            s_lo += __shfl_xor_sync(0xffffffffu, s_lo, 2);
            s_hi += __shfl_xor_sync(0xffffffffu, s_hi, 1);
            s_hi += __shfl_xor_sync(0xffffffffu, s_hi, 2);
            float rlo = donorm ? rsqrtf(s_lo) : 1.f;
            float rhi = donorm ? rsqrtf(s_hi) : 1.f;
            int m = m0 + wm * 64 + mb * 16 + (lane >> 2);
#pragma unroll
            for (int nb = 0; nb < 4; nb++) {
                int j = j0 + wn * 32 + nb * 8 + (lane & 3) * 2;
                float2 o0 = make_float2(vlo[nb][0] * rlo, vlo[nb][1] * rlo);
                float2 o1 = make_float2(vhi[nb][0] * rhi, vhi[nb][1] * rhi);
                *(float2*)(g_qkv + (size_t)m * J3 + j) = o0;
                *(float2*)(g_qkv + (size_t)(m + 8) * J3 + j) = o1;
            }
        }
    } else {
        // transpose through smem (aliasing A/B stages) for coalesced NCHW stores
        float (*Cs)[136] = reinterpret_cast<float (*)[136]>(&As[0][0]);
        for (int slice = 0; slice < 4; slice++) {
            if (wn == slice) {
#pragma unroll
                for (int mb = 0; mb < 4; mb++)
#pragma unroll
                    for (int nb = 0; nb < 4; nb++) {
                        int jl = nb * 8 + (lane & 3) * 2;
                        int r = wm * 64 + mb * 16 + (lane >> 2);
                        Cs[jl][r]         = acc[mb][nb][0];
                        Cs[jl + 1][r]     = acc[mb][nb][1];
                        Cs[jl][r + 8]     = acc[mb][nb][2];
                        Cs[jl + 1][r + 8] = acc[mb][nb][3];
                    }
            }
            __syncthreads();
#pragma unroll
            for (int rr = 0; rr < 4; rr++) {
                int idx = rr * 256 + tid;
                int j = idx >> 5, f4 = idx & 31;
                float b = __ldg(bias + j0 + slice * 32 + j);
                float4 v = *(float4*)&Cs[j][f4 * 4];
                v.x += b; v.y += b; v.z += b; v.w += b;
                *(float4*)(outp + (size_t)(n * CC + j0 + slice * 32 + j) * LL + l0 + f4 * 4) = v;
            }
            __syncthreads();
        }
    }
}

// ===================== attn =====================
__global__ void k_zero_attn() {
    int i = blockIdx.x * 256 + threadIdx.x;
    if (i < NH * DD * DD) g_attn[i] = 0.f;
}
__global__ __launch_bounds__(256) void k_attn() {
    __shared__ float ks[32][32];
    __shared__ float vs[32][32];
    const int nh = blockIdx.x, chunk = blockIdx.y;
    const int n = nh >> 3, hh = nh & 7;
    const int tid = threadIdx.x;
    const int d = tid >> 3, e4 = tid & 7;
    const int lbase = chunk * (LL / SPLIT);
    const float* base = g_qkv + (size_t)n * LL * J3 + hh * DD;
    const int r = tid >> 3, c4 = (tid & 7) * 4;
    float acc[4] = {};
    for (int t0 = 0; t0 < LL / SPLIT; t0 += 32) {
        const float* rp = base + (size_t)(lbase + t0 + r) * J3;
        *(float4*)&ks[r][c4] = *(const float4*)(rp + CC + c4);
        *(float4*)&vs[r][c4] = *(const float4*)(rp + 2 * CC + c4);
        __syncthreads();
#pragma unroll
        for (int rr = 0; rr < 32; rr++) {
            float kk = ks[rr][d];
            float4 vv = *(const float4*)&vs[rr][e4 * 4];
            acc[0] = fmaf(kk, vv.x, acc[0]); acc[1] = fmaf(kk, vv.y, acc[1]);
            acc[2] = fmaf(kk, vv.z, acc[2]); acc[3] = fmaf(kk, vv.w, acc[3]);
        }
        __syncthreads();
    }
    float* ap = g_attn + nh * (DD * DD) + d * DD + e4 * 4;
    atomicAdd(ap + 0, acc[0]); atomicAdd(ap + 1, acc[1]);
    atomicAdd(ap + 2, acc[2]); atomicAdd(ap + 3, acc[3]);
}

// ===================== fused epilogue -> split mid =====================
__device__ __forceinline__ uint32_t pk2(float a, float b) {
    __nv_bfloat162 t = __floats2bfloat162_rn(a, b);
    return *reinterpret_cast<uint32_t*>(&t);
}
__global__ __launch_bounds__(256) void k_out(const float* __restrict__ wdc) {
    __shared__ float att[32][32];
    __shared__ float q_s[TOK][33];
    __shared__ float v_s[TOK + 8][32];
    __shared__ float ws9[9];
    const int bid = blockIdx.x;
    const int nh = bid >> 5, ltile = bid & 31;
    const int n = nh >> 3, hh = nh & 7;
    const int tid = threadIdx.x;
    const int l0 = ltile * TOK;

    const float INV_PI = 0.3183098861837907f;
    for (int i = tid; i < 1024; i += 256) ((float*)att)[i] = g_attn[nh * 1024 + i] * INV_PI;
    if (tid < 9) ws9[tid] = wdc[hh * 9 + tid];

    const float* qb = g_qkv + (size_t)n * LL * J3 + hh * DD;
    for (int i = tid; i < TOK * 8; i += 256) {
        int r = i >> 3, c4 = (i & 7) * 4;
        float4 v4 = *(const float4*)(qb + (size_t)(l0 + r) * J3 + c4);
        q_s[r][c4 + 0] = v4.x; q_s[r][c4 + 1] = v4.y;
        q_s[r][c4 + 2] = v4.z; q_s[r][c4 + 3] = v4.w;
    }
    for (int i = tid; i < (TOK + 8) * 8; i += 256) {
        int r = i >> 3, c4 = i & 7;
        int l = l0 - 4 + r;
        float4 v4 = make_float4(0.f, 0.f, 0.f, 0.f);
        if ((unsigned)l < (unsigned)LL)
            v4 = *(const float4*)(qb + (size_t)l * J3 + 2 * CC + c4 * 4);
        *(float4*)&v_s[r][(c4 ^ (r & 7)) * 4] = v4;
    }
    __syncthreads();

    const int t = tid >> 1, h = tid & 1;
    const int l = l0 + t;

    float4 o[4];
    {
        int r = t + 4;
#pragma unroll
        for (int j = 0; j < 4; j++) {
            float4 vv = *(const float4*)&v_s[r][((h * 4 + j) ^ (r & 7)) * 4];
            o[j] = make_float4(0.5f * vv.x, 0.5f * vv.y, 0.5f * vv.z, 0.5f * vv.w);
        }
    }
#pragma unroll 4
    for (int d = 0; d < 32; d++) {
        float qd = q_s[t][d];
#pragma unroll
        for (int j = 0; j < 4; j++) {
            float4 a = *(const float4*)&att[d][h * 16 + j * 4];
            o[j].x = fmaf(qd, a.x, o[j].x); o[j].y = fmaf(qd, a.y, o[j].y);
            o[j].z = fmaf(qd, a.z, o[j].z); o[j].w = fmaf(qd, a.w, o[j].w);
        }
    }
    float s = 0.f;
#pragma unroll
    for (int j = 0; j < 4; j++)
        s += o[j].x * o[j].x + o[j].y * o[j].y + o[j].z * o[j].z + o[j].w * o[j].w;
    s += __shfl_xor_sync(0xffffffffu, s, 1);
    float rn = rsqrtf(s);
#pragma unroll
    for (int j = 0; j < 4; j++) { o[j].x *= rn; o[j].y *= rn; o[j].z *= rn; o[j].w *= rn; }
#pragma unroll
    for (int tap = 0; tap < 9; tap++) {
        float wt = ws9[tap];
        int r = t + tap;
#pragma unroll
        for (int j = 0; j < 4; j++) {
            float4 vv = *(const float4*)&v_s[r][((h * 4 + j) ^ (r & 7)) * 4];
            o[j].x = fmaf(wt, vv.x, o[j].x); o[j].y = fmaf(wt, vv.y, o[j].y);
            o[j].z = fmaf(wt, vv.z, o[j].z); o[j].w = fmaf(wt, vv.w, o[j].w);
        }
    }
    float f[16] = {o[0].x, o[0].y, o[0].z, o[0].w, o[1].x, o[1].y, o[1].z, o[1].w,
                   o[2].x, o[2].y, o[2].z, o[2].w, o[3].x, o[3].y, o[3].z, o[3].w};
    float fh[16], fl[16];
#pragma unroll
    for (int i = 0; i < 16; i++) {
        __nv_bfloat16 hb = __float2bfloat16(f[i]);
        fh[i] = __bfloat162float(hb);
        fl[i] = f[i] - fh[i];
    }
    const int cb = hh * 32 + h * 16;
    __nv_bfloat16* row = g_mids + (size_t)(n * LL + l) * 512;
    uint4 hi0 = make_uint4(pk2(fh[0], fh[1]), pk2(fh[2], fh[3]), pk2(fh[4], fh[5]), pk2(fh[6], fh[7]));
    uint4 hi1 = make_uint4(pk2(fh[8], fh[9]), pk2(fh[10], fh[11]), pk2(fh[12], fh[13]), pk2(fh[14], fh[15]));
    uint4 lo0 = make_uint4(pk2(fl[0], fl[1]), pk2(fl[2], fl[3]), pk2(fl[4], fl[5]), pk2(fl[6], fl[7]));
    uint4 lo1 = make_uint4(pk2(fl[8], fl[9]), pk2(fl[10], fl[11]), pk2(fl[12], fl[13]), pk2(fl[14], fl[15]));
    *(uint4*)(row + cb) = hi0;
    *(uint4*)(row + cb + 8) = hi1;
    *(uint4*)(row + 256 + cb) = lo0;
    *(uint4*)(row + 256 + cb + 8) = lo1;
}

// ===================== launch =====================
extern "C" void kernel_launch(void* const* d_in, const int* in_sizes, int n_in,
                              void* d_out, int out_size) {
    const float* x      = (const float*)d_in[0];
    const float* w_qkv  = (const float*)d_in[1];
    const float* b_qkv  = (const float*)d_in[2];
    const float* w_proj = (const float*)d_in[3];
    const float* b_proj = (const float*)d_in[4];
    const float* w_dc   = (const float*)d_in[5];
    float* out = (float*)d_out;
    (void)in_sizes; (void)n_in; (void)out_size;

    k_split_x<<<dim3(LL / 32, CC / 32, NB), dim3(32, 8)>>>(x);
    k_split_wq<<<(J3 * 256) / 256, 256>>>(w_qkv);
    k_split_wp<<<(CC * 256) / 256, 256>>>(w_proj);

    k_mma<true><<<dim3(J3 / 128, (NB * LL) / 128), 256>>>(b_qkv, nullptr);

    k_zero_attn<<<(NH * DD * DD + 255) / 256, 256>>>();
    k_attn<<<dim3(NH, SPLIT), 256>>>();
    k_out<<<NH * (LL / TOK), 256>>>(w_dc);

    k_mma<false><<<dim3(CC / 128, (NB * LL) / 128), 256>>>(b_proj, out);
}